// round 2
// baseline (speedup 1.0000x reference)
#include <cuda_runtime.h>
#include <math.h>

// Problem constants
#define BB   4
#define SS   2048
#define EE   256
#define HH   8
#define DDIM 32
#define WWIN 33
#define PADW 16
#define KKEY 2016        // S - W + 1
#define NBH  32          // B*H

// Attention tiling
#define TQ   128
#define TK   64
#define QSR  (TQ + 32)   // 160 q rows incl. halo
#define KSR  (TK + 32)   // 96 k rows incl. halo
#define LDQ  33          // padded row stride for q/k/vs tiles
#define LDG  97          // padded row stride for G
#define LDP  65          // padded row stride for P
#define NTH  512

// Shared memory layout (floats)
#define OFF_QS  0
#define OFF_KS  (OFF_QS + QSR * LDQ)        // 5280
#define OFF_VS  (OFF_KS + KSR * LDQ)        // 8448
#define OFF_G   (OFF_VS + TK  * LDQ)        // 10560
#define OFF_P   (OFF_G  + QSR * LDG)        // 26080
#define OFF_DEN (OFF_P  + TQ  * LDP)        // 34400
#define SMEM_FLOATS (OFF_DEN + TQ)          // 34528
#define SMEM_BYTES  (SMEM_FLOATS * 4)       // 138112 B

// Scratch (device globals: no runtime allocation allowed)
__device__ float g_q[NBH * SS * DDIM];
__device__ float g_k[NBH * SS * DDIM];
__device__ float g_v[NBH * SS * DDIM];
__device__ float g_vsum[NBH * KKEY * DDIM];

// ---------------------------------------------------------------------------
// Kernel 1: fused QKV projection.  out[8192, 768] = x[8192,256] @ [Wq|Wk|Wv]
// + bias, scattered into per-head [bh][s][d] layout.
// ---------------------------------------------------------------------------
__global__ __launch_bounds__(256) void proj_kernel(
    const float* __restrict__ x,
    const float* __restrict__ Wq, const float* __restrict__ bq,
    const float* __restrict__ Wk, const float* __restrict__ bk,
    const float* __restrict__ Wv, const float* __restrict__ bv)
{
    __shared__ float xs[64][17];
    __shared__ float ws[16][65];

    int tid = threadIdx.x;            // 256 threads
    int m0  = blockIdx.y * 64;        // row tile
    int n0  = blockIdx.x * 64;        // col tile (within 768)
    int msel = n0 >> 8;               // 0=q, 1=k, 2=v
    const float* Wsel = (msel == 0) ? Wq : (msel == 1) ? Wk : Wv;
    const float* bsel = (msel == 0) ? bq : (msel == 1) ? bk : bv;
    int ncol0 = n0 & 255;

    int ty = tid >> 4;                // 0..15 (m dir)
    int tx = tid & 15;                // 0..15 (n dir)

    float acc[4][4];
#pragma unroll
    for (int i = 0; i < 4; i++)
#pragma unroll
        for (int j = 0; j < 4; j++) acc[i][j] = 0.f;

    for (int k0 = 0; k0 < EE; k0 += 16) {
        {   // load x tile 64x16 (float4 per thread)
            int row = tid >> 2;
            int kk  = (tid & 3) * 4;
            float4 xv = *reinterpret_cast<const float4*>(
                &x[(size_t)(m0 + row) * EE + k0 + kk]);
            xs[row][kk]     = xv.x; xs[row][kk + 1] = xv.y;
            xs[row][kk + 2] = xv.z; xs[row][kk + 3] = xv.w;
        }
        {   // load W tile 16x64
            int kk = tid >> 4;
            int nn = (tid & 15) * 4;
            float4 wv = *reinterpret_cast<const float4*>(
                &Wsel[(size_t)(k0 + kk) * EE + ncol0 + nn]);
            ws[kk][nn]     = wv.x; ws[kk][nn + 1] = wv.y;
            ws[kk][nn + 2] = wv.z; ws[kk][nn + 3] = wv.w;
        }
        __syncthreads();
#pragma unroll
        for (int kk = 0; kk < 16; kk++) {
            float a[4], b[4];
#pragma unroll
            for (int i = 0; i < 4; i++) a[i] = xs[ty * 4 + i][kk];
#pragma unroll
            for (int j = 0; j < 4; j++) b[j] = ws[kk][tx * 4 + j];
#pragma unroll
            for (int i = 0; i < 4; i++)
#pragma unroll
                for (int j = 0; j < 4; j++) acc[i][j] += a[i] * b[j];
        }
        __syncthreads();
    }

    float* dst = (msel == 0) ? g_q : (msel == 1) ? g_k : g_v;
#pragma unroll
    for (int i = 0; i < 4; i++) {
        int m = m0 + ty * 4 + i;
        int b = m >> 11;              // / 2048
        int s = m & 2047;
#pragma unroll
        for (int j = 0; j < 4; j++) {
            int e = ncol0 + tx * 4 + j;
            int h = e >> 5;
            int d = e & 31;
            float val = acc[i][j] + bsel[e];
            dst[(((size_t)(b * HH + h) * SS + s) * DDIM) + d] = val;
        }
    }
}

// ---------------------------------------------------------------------------
// Kernel 2: vsum[bh][k][d] = sum_{w<33} v[bh][k+w][d]
// ---------------------------------------------------------------------------
__global__ void vsum_kernel()
{
    int idx = blockIdx.x * blockDim.x + threadIdx.x;
    const int total = NBH * KKEY * DDIM;
    if (idx >= total) return;
    int d  = idx & 31;
    int k  = (idx >> 5) % KKEY;
    int bh = idx / (DDIM * KKEY);
    const float* vp = &g_v[((size_t)bh * SS + k) * DDIM + d];
    float s = 0.f;
#pragma unroll
    for (int w = 0; w < WWIN; w++) s += vp[w * DDIM];
    g_vsum[idx] = s;
}

// ---------------------------------------------------------------------------
// Kernel 3: attention via Gram-diagonal reformulation + no-max softmax.
// One block per (q-tile of 128, bh). Loops over 32 key tiles of 64.
// ---------------------------------------------------------------------------
__global__ __launch_bounds__(NTH, 1) void attn_kernel(float* __restrict__ out)
{
    extern __shared__ float sm[];
    float* qs  = sm + OFF_QS;   // [160][33]
    float* ks  = sm + OFF_KS;   // [96][33]
    float* vs  = sm + OFF_VS;   // [64][33]
    float* G   = sm + OFF_G;    // [160][97]
    float* P   = sm + OFF_P;    // [128][65]
    float* den = sm + OFF_DEN;  // [128]

    const float scale = 0.17677669529663687f;  // 1/sqrt(32)
    int tid = threadIdx.x;
    int q0  = blockIdx.x * TQ;
    int bh  = blockIdx.y;
    const float* qg = g_q    + (size_t)bh * SS   * DDIM;
    const float* kg = g_k    + (size_t)bh * SS   * DDIM;
    const float* vg = g_vsum + (size_t)bh * KKEY * DDIM;

    // Load q halo tile (rows q0-16 .. q0+143), zero-padded (matches jnp.pad)
    for (int idx = tid; idx < QSR * DDIM; idx += NTH) {
        int i = idx >> 5, d = idx & 31;
        int gq = q0 - PADW + i;
        qs[i * LDQ + d] = (gq >= 0 && gq < SS) ? qg[gq * DDIM + d] : 0.f;
    }
    if (tid < TQ) den[tid] = 0.f;

    // PV ownership: thread owns rows [qgrp*8 .. qgrp*8+7], column dcol
    int dcol = tid & 31;
    int qgrp = tid >> 5;     // 0..15
    float num[8];
#pragma unroll
    for (int r = 0; r < 8; r++) num[r] = 0.f;

    // Gram-GEMM thread coords: 32 (i-groups of 5) x 16 (j-groups of 6)
    int tx = tid & 15;
    int ty = tid >> 4;

    for (int kt = 0; kt < 32; kt++) {
        int k0 = kt * TK;
        __syncthreads();   // prev-iter P/vs consumed; also covers qs/den init

        // Load k halo tile + vsum tile
        for (int idx = tid; idx < KSR * DDIM; idx += NTH) {
            int j = idx >> 5, d = idx & 31;
            int gk = k0 + j;
            ks[j * LDQ + d] = (gk < SS) ? kg[gk * DDIM + d] : 0.f;
        }
        for (int idx = tid; idx < TK * DDIM; idx += NTH) {
            int j = idx >> 5, d = idx & 31;
            int gk = k0 + j;
            vs[j * LDQ + d] = (gk < KKEY) ? vg[gk * DDIM + d] : 0.f;
        }
        __syncthreads();

        // Phase B: G[i][j] = qs[i] . ks[j]   (160x96, D=32 contraction)
        {
            float acc[5][6];
#pragma unroll
            for (int i = 0; i < 5; i++)
#pragma unroll
                for (int j = 0; j < 6; j++) acc[i][j] = 0.f;
            int ib = ty * 5, jb = tx * 6;
#pragma unroll
            for (int d = 0; d < DDIM; d++) {
                float a[5], b[6];
#pragma unroll
                for (int i = 0; i < 5; i++) a[i] = qs[(ib + i) * LDQ + d];
#pragma unroll
                for (int j = 0; j < 6; j++) b[j] = ks[(jb + j) * LDQ + d];
#pragma unroll
                for (int i = 0; i < 5; i++)
#pragma unroll
                    for (int j = 0; j < 6; j++) acc[i][j] += a[i] * b[j];
            }
#pragma unroll
            for (int i = 0; i < 5; i++)
#pragma unroll
                for (int j = 0; j < 6; j++)
                    G[(ib + i) * LDG + (jb + j)] = acc[i][j];
        }
        __syncthreads();

        // Phase C: per-thread diagonal sliding-window sum + exp -> P
        // scores(qq,kk) = sum_{w<33} G[qq+w][kk+w]
        if (tid < TQ + TK - 1) {
            int qq, kk, len;
            if (tid < TQ) { qq = tid; kk = 0; len = min(TK, TQ - tid); }
            else          { qq = 0;  kk = tid - TQ + 1; len = TK - kk; }
            float s = 0.f;
#pragma unroll
            for (int w = 0; w < WWIN; w++)
                s += G[(qq + w) * LDG + (kk + w)];
            for (int t = 0; t < len; t++) {
                if (t) {
                    s += G[(qq + t + 32) * LDG + (kk + t + 32)]
                       - G[(qq + t - 1) * LDG + (kk + t - 1)];
                }
                float p = (k0 + kk + t < KKEY) ? __expf(s * scale) : 0.f;
                P[(qq + t) * LDP + (kk + t)] = p;
            }
        }
        __syncthreads();

        // Phase D: denominator + PV accumulation
        if (tid < TQ) {
            float dsum = 0.f;
#pragma unroll 8
            for (int j = 0; j < TK; j++) dsum += P[tid * LDP + j];
            den[tid] += dsum;
        }
        {
            int qb = qgrp * 8;
#pragma unroll 4
            for (int j = 0; j < TK; j++) {
                float vv = vs[j * LDQ + dcol];
#pragma unroll
                for (int r = 0; r < 8; r++)
                    num[r] += P[(qb + r) * LDP + j] * vv;
            }
        }
    }
    __syncthreads();

    // Write output: out[b, s, h*32+d]
    int b = bh >> 3, h = bh & 7;
    int qb = qgrp * 8;
#pragma unroll
    for (int r = 0; r < 8; r++) {
        int q = q0 + qb + r;
        out[((size_t)(b * SS + q) * EE) + h * DDIM + dcol] =
            num[r] / den[qb + r];
    }
}

// ---------------------------------------------------------------------------
extern "C" void kernel_launch(void* const* d_in, const int* in_sizes, int n_in,
                              void* d_out, int out_size)
{
    const float* x  = (const float*)d_in[0];
    const float* Wq = (const float*)d_in[1];
    const float* bq = (const float*)d_in[2];
    const float* Wk = (const float*)d_in[3];
    const float* bk = (const float*)d_in[4];
    const float* Wv = (const float*)d_in[5];
    const float* bv = (const float*)d_in[6];
    float* out = (float*)d_out;

    // 1) QKV projections: grid (768/64, 8192/64)
    {
        dim3 grid(12, 128);
        proj_kernel<<<grid, 256>>>(x, Wq, bq, Wk, bk, Wv, bv);
    }
    // 2) sliding V sums
    {
        const int total = NBH * KKEY * DDIM;
        vsum_kernel<<<(total + 255) / 256, 256>>>();
    }
    // 3) attention
    {
        cudaFuncSetAttribute(attn_kernel,
                             cudaFuncAttributeMaxDynamicSharedMemorySize,
                             SMEM_BYTES);
        dim3 grid(SS / TQ, NBH);   // (16, 32)
        attn_kernel<<<grid, NTH, SMEM_BYTES>>>(out);
    }
}

// round 4
// speedup vs baseline: 1.5930x; 1.5930x over previous
#include <cuda_runtime.h>
#include <cuda_bf16.h>
#include <cstdint>

#define NBH   32
#define SSZ   2048
#define EE    256
#define HH    8
#define KKEY  2016
#define WWIN  33
#define TQ    96
#define NKT   21
#define NQT   22
#define NTH   512
#define NCHUNK 381
#define SCALE 0.17677669529663687f

#define QLD   104     // bf16 stride for QA/KB/P/V tiles
#define QLDW  52      // same, in 32-bit words
#define GLD   132     // fp32 word stride for G

// smem byte offsets
#define OFF_TQQ  0
#define OFF_TKK  768
#define OFF_TLEN 1536
#define OFF_DEN  2304
#define OFF_QA   2688       // 128 x 208B = 26624
#define OFF_KB   29312      // 128 x 208B
#define OFF_G    55936      // 128 x 132 x 4 = 67584
#define OFF_PH   123520     // 96 x 208B = 19968
#define OFF_PL   143488
#define OFF_VH   163456     // 40 x 208B = 8320
#define OFF_VL   171776
#define SMEM_TOTAL 180096

// device scratch (no runtime allocation allowed)
__device__ __align__(16) __nv_bfloat16 g_qA[(size_t)NBH * SSZ * 96];
__device__ __align__(16) __nv_bfloat16 g_kB[(size_t)NBH * SSZ * 96];
__device__ __align__(16) float         g_v [(size_t)NBH * SSZ * 32];
__device__ __align__(16) __nv_bfloat16 g_vsH[(size_t)NBH * 32 * KKEY];
__device__ __align__(16) __nv_bfloat16 g_vsL[(size_t)NBH * 32 * KKEY];

// m16n8k16 bf16 MMA, fp32 accum
__device__ __forceinline__ void mma16816(float* c, uint32_t a0, uint32_t a1,
                                         uint32_t a2, uint32_t a3,
                                         uint32_t b0, uint32_t b1)
{
    asm volatile(
        "mma.sync.aligned.m16n8k16.row.col.f32.bf16.bf16.f32 "
        "{%0,%1,%2,%3}, {%4,%5,%6,%7}, {%8,%9}, {%0,%1,%2,%3};"
        : "+f"(c[0]), "+f"(c[1]), "+f"(c[2]), "+f"(c[3])
        : "r"(a0), "r"(a1), "r"(a2), "r"(a3), "r"(b0), "r"(b1));
}

// ---------------------------------------------------------------------------
// Kernel 1: QKV projection -> packed bf16-split layouts (96-wide rows)
// Q rows: [hi(32)|lo(32)|hi(32)]   K rows: [hi|hi|lo]   V: fp32
// ---------------------------------------------------------------------------
__global__ __launch_bounds__(256) void proj_kernel(
    const float* __restrict__ x,
    const float* __restrict__ Wq, const float* __restrict__ bq,
    const float* __restrict__ Wk, const float* __restrict__ bk,
    const float* __restrict__ Wv, const float* __restrict__ bv)
{
    __shared__ float xs[64][17];
    __shared__ float ws[16][65];
    int tid = threadIdx.x;
    int m0 = blockIdx.y * 64;
    int n0 = blockIdx.x * 64;
    int msel = n0 >> 8;
    const float* Wsel = (msel == 0) ? Wq : (msel == 1) ? Wk : Wv;
    const float* bsel = (msel == 0) ? bq : (msel == 1) ? bk : bv;
    int ncol0 = n0 & 255;
    int ty = tid >> 4, tx = tid & 15;

    float acc[4][4];
#pragma unroll
    for (int i = 0; i < 4; i++)
#pragma unroll
        for (int j = 0; j < 4; j++) acc[i][j] = 0.f;

    for (int k0 = 0; k0 < EE; k0 += 16) {
        {
            int row = tid >> 2, kk = (tid & 3) * 4;
            float4 xv = *reinterpret_cast<const float4*>(
                &x[(size_t)(m0 + row) * EE + k0 + kk]);
            xs[row][kk] = xv.x; xs[row][kk + 1] = xv.y;
            xs[row][kk + 2] = xv.z; xs[row][kk + 3] = xv.w;
        }
        {
            int kk = tid >> 4, nn = (tid & 15) * 4;
            float4 wv = *reinterpret_cast<const float4*>(
                &Wsel[(size_t)(k0 + kk) * EE + ncol0 + nn]);
            ws[kk][nn] = wv.x; ws[kk][nn + 1] = wv.y;
            ws[kk][nn + 2] = wv.z; ws[kk][nn + 3] = wv.w;
        }
        __syncthreads();
#pragma unroll
        for (int kk = 0; kk < 16; kk++) {
            float a[4], b[4];
#pragma unroll
            for (int i = 0; i < 4; i++) a[i] = xs[ty * 4 + i][kk];
#pragma unroll
            for (int j = 0; j < 4; j++) b[j] = ws[kk][tx * 4 + j];
#pragma unroll
            for (int i = 0; i < 4; i++)
#pragma unroll
                for (int j = 0; j < 4; j++) acc[i][j] += a[i] * b[j];
        }
        __syncthreads();
    }

#pragma unroll
    for (int i = 0; i < 4; i++) {
        int m = m0 + ty * 4 + i;
        int b = m >> 11, s = m & 2047;
#pragma unroll
        for (int j = 0; j < 4; j++) {
            int e = ncol0 + tx * 4 + j;
            int h = e >> 5, d = e & 31;
            float val = acc[i][j] + bsel[e];
            if (msel == 2) {
                g_v[(((size_t)(b * HH + h) * SSZ + s) * 32) + d] = val;
            } else {
                __nv_bfloat16 hi = __float2bfloat16(val);
                __nv_bfloat16 lo = __float2bfloat16(val - __bfloat162float(hi));
                size_t rb = ((size_t)(b * HH + h) * SSZ + s) * 96;
                if (msel == 0) {          // Q: [hi | lo | hi]
                    g_qA[rb + d] = hi;
                    g_qA[rb + 32 + d] = lo;
                    g_qA[rb + 64 + d] = hi;
                } else {                  // K: [hi | hi | lo]
                    g_kB[rb + d] = hi;
                    g_kB[rb + 32 + d] = hi;
                    g_kB[rb + 64 + d] = lo;
                }
            }
        }
    }
}

// ---------------------------------------------------------------------------
// Kernel 2: transposed split sliding V-sums: g_vs*[bh][d][k] = sum_w v[k+w][d]
// ---------------------------------------------------------------------------
__global__ void vsum_kernel()
{
    int idx = blockIdx.x * blockDim.x + threadIdx.x;
    const int total = NBH * KKEY * 32;
    if (idx >= total) return;
    int d = idx & 31;
    int k = (idx >> 5) % KKEY;
    int bh = idx / (32 * KKEY);
    const float* vp = &g_v[((size_t)bh * SSZ + k) * 32 + d];
    float s = 0.f;
#pragma unroll
    for (int w = 0; w < WWIN; w++) s += vp[w * 32];
    __nv_bfloat16 hi = __float2bfloat16(s);
    __nv_bfloat16 lo = __float2bfloat16(s - __bfloat162float(hi));
    size_t o = ((size_t)bh * 32 + d) * KKEY + k;
    g_vsH[o] = hi;
    g_vsL[o] = lo;
}

// ---------------------------------------------------------------------------
// Kernel 3: HMMA attention (Gram-diagonal + no-max softmax)
// ---------------------------------------------------------------------------
__global__ __launch_bounds__(NTH, 1) void attn_kernel(float* __restrict__ out)
{
    extern __shared__ char sm[];
    uint16_t* tqq  = (uint16_t*)(sm + OFF_TQQ);
    uint16_t* tkk  = (uint16_t*)(sm + OFF_TKK);
    uint16_t* tlen = (uint16_t*)(sm + OFF_TLEN);
    float* den_s = (float*)(sm + OFF_DEN);
    float* G = (float*)(sm + OFF_G);
    const uint32_t* QAw = (const uint32_t*)(sm + OFF_QA);
    const uint32_t* KBw = (const uint32_t*)(sm + OFF_KB);
    const uint32_t* PHw = (const uint32_t*)(sm + OFF_PH);
    const uint32_t* PLw = (const uint32_t*)(sm + OFF_PL);
    const uint32_t* VHw = (const uint32_t*)(sm + OFF_VH);
    const uint32_t* VLw = (const uint32_t*)(sm + OFF_VL);
    __nv_bfloat16* PH = (__nv_bfloat16*)(sm + OFF_PH);
    __nv_bfloat16* PL = (__nv_bfloat16*)(sm + OFF_PL);

    int tid = threadIdx.x;
    int w = tid >> 5, lane = tid & 31;
    int g = lane >> 2, t = lane & 3;
    int qt = blockIdx.x, bh = blockIdx.y;
    int q0 = qt * TQ;

    if (tid == 0) {           // diagonal chunk table
        int c = 0;
        for (int d = -95; d <= 95; d++) {
            int ad = d < 0 ? -d : d;
            int L = 96 - ad;
            int qs0 = d > 0 ? d : 0, ks0 = d > 0 ? 0 : -d;
            for (int t0 = 0; t0 < L; t0 += 32) {
                tqq[c] = (uint16_t)(qs0 + t0);
                tkk[c] = (uint16_t)(ks0 + t0);
                int l = L - t0; tlen[c] = (uint16_t)(l < 32 ? l : 32);
                c++;
            }
        }
    }

    // Q halo tile (rows q0-16 .. q0+111), zero-padded
    {
        const uint4* qsrc = (const uint4*)(g_qA + (size_t)bh * SSZ * 96);
        for (int idx = tid; idx < 128 * 12; idx += NTH) {
            int r = idx / 12, cb = idx % 12;
            int gq = q0 - 16 + r;
            uint4 v = make_uint4(0, 0, 0, 0);
            if (gq >= 0 && gq < SSZ) v = qsrc[(size_t)gq * 12 + cb];
            *(uint4*)(sm + OFF_QA + r * 208 + cb * 16) = v;
        }
    }
    // V rows 32..39: VH row 32 = ones (denominator), everything else zero
    for (int idx = tid; idx < 208; idx += NTH) {
        int tt = idx / 104, rem = idx % 104;
        int r = 32 + rem / 13, cb = rem % 13;
        uint4 v = make_uint4(0, 0, 0, 0);
        if (tt == 0 && r == 32)
            v = make_uint4(0x3F803F80u, 0x3F803F80u, 0x3F803F80u, 0x3F803F80u);
        *(uint4*)(sm + (tt ? OFF_VL : OFF_VH) + r * 208 + cb * 16) = v;
    }

    // warp roles
    int mw = w >> 2, nw = w & 3;       // G: 4x4 warp grid, 32x32 tiles
    int r0 = mw * 32, kb = nw * 32;
    int mp = w >> 1, ng = w & 1;       // PV: warps 0..11
    int ntc = ng ? 2 : 3;

    float acc[3][4];
#pragma unroll
    for (int i = 0; i < 3; i++)
#pragma unroll
        for (int j = 0; j < 4; j++) acc[i][j] = 0.f;

    const uint4* ksrc = (const uint4*)(g_kB + (size_t)bh * SSZ * 96);

    for (int kt = 0; kt < NKT; kt++) {
        int k0 = kt * TQ;
        __syncthreads();   // prev iter's PV reads of V / G reads of KB done

        // K tile: rows k0..k0+127 (always < 2048)
        for (int idx = tid; idx < 1536; idx += NTH) {
            int r = idx / 12, cb = idx % 12;
            *(uint4*)(sm + OFF_KB + r * 208 + cb * 16) =
                ksrc[(size_t)(k0 + r) * 12 + cb];
        }
        // V tiles: rows d=0..31, 96 keys
        for (int idx = tid; idx < 768; idx += NTH) {
            int tt = idx / 384, rem = idx % 384;
            int d = rem / 12, cb = rem % 12;
            const __nv_bfloat16* src = (tt ? g_vsL : g_vsH)
                + ((size_t)bh * 32 + d) * KKEY + k0 + cb * 8;
            *(uint4*)(sm + (tt ? OFF_VL : OFF_VH) + d * 208 + cb * 16) =
                *(const uint4*)src;
        }
        __syncthreads();

        // --- G = QA @ KB^T  (M=128, N=128, K=96 packed split) ---
        {
            float c[2][4][4];
#pragma unroll
            for (int mi = 0; mi < 2; mi++)
#pragma unroll
                for (int ni = 0; ni < 4; ni++)
#pragma unroll
                    for (int j = 0; j < 4; j++) c[mi][ni][j] = 0.f;
#pragma unroll
            for (int ks = 0; ks < 6; ks++) {
                uint32_t a[2][4];
#pragma unroll
                for (int mi = 0; mi < 2; mi++) {
                    int rb = (r0 + mi * 16 + g) * QLDW + ks * 8 + t;
                    a[mi][0] = QAw[rb];
                    a[mi][1] = QAw[rb + 8 * QLDW];
                    a[mi][2] = QAw[rb + 4];
                    a[mi][3] = QAw[rb + 8 * QLDW + 4];
                }
#pragma unroll
                for (int ni = 0; ni < 4; ni++) {
                    int bb = (kb + ni * 8 + g) * QLDW + ks * 8 + t;
                    uint32_t b0 = KBw[bb], b1 = KBw[bb + 4];
                    mma16816(c[0][ni], a[0][0], a[0][1], a[0][2], a[0][3], b0, b1);
                    mma16816(c[1][ni], a[1][0], a[1][1], a[1][2], a[1][3], b0, b1);
                }
            }
#pragma unroll
            for (int mi = 0; mi < 2; mi++)
#pragma unroll
                for (int ni = 0; ni < 4; ni++) {
                    int r = r0 + mi * 16 + g;
                    int col = kb + ni * 8 + 2 * t;
                    *(float2*)&G[r * GLD + col] =
                        make_float2(c[mi][ni][0], c[mi][ni][1]);
                    *(float2*)&G[(r + 8) * GLD + col] =
                        make_float2(c[mi][ni][2], c[mi][ni][3]);
                }
        }
        __syncthreads();

        // --- diagonal sliding-window scores + exp -> P split ---
        if (tid < NCHUNK) {
            int qq = tqq[tid], kk = tkk[tid], len = tlen[tid];
            float s = 0.f;
#pragma unroll
            for (int ww = 0; ww < WWIN; ww++)
                s += G[(qq + ww) * GLD + kk + ww];
            for (int u = 0; u < len; u++) {
                if (u) s += G[(qq + u + 32) * GLD + (kk + u + 32)]
                          - G[(qq + u - 1) * GLD + (kk + u - 1)];
                float p = __expf(s * SCALE);
                __nv_bfloat16 hi = __float2bfloat16(p);
                __nv_bfloat16 lo = __float2bfloat16(p - __bfloat162float(hi));
                int off = (qq + u) * QLD + (kk + u);
                PH[off] = hi;
                PL[off] = lo;
            }
        }
        __syncthreads();

        // --- PV accumulate: D += Phi@Vhi + Plo@Vhi + Phi@Vlo ---
        if (w < 12) {
#pragma unroll
            for (int pass = 0; pass < 3; pass++) {
                const uint32_t* Aw = (pass == 1) ? PLw : PHw;
                const uint32_t* Bw = (pass == 2) ? VLw : VHw;
#pragma unroll
                for (int ks = 0; ks < 6; ks++) {
                    int ab = (mp * 16 + g) * QLDW + ks * 8 + t;
                    uint32_t a0 = Aw[ab], a1 = Aw[ab + 8 * QLDW];
                    uint32_t a2 = Aw[ab + 4], a3 = Aw[ab + 8 * QLDW + 4];
#pragma unroll
                    for (int nt = 0; nt < 3; nt++) {
                        if (nt < ntc) {
                            int tile = ng ? (3 + nt) : nt;
                            int bb = (tile * 8 + g) * QLDW + ks * 8 + t;
                            mma16816(acc[nt], a0, a1, a2, a3, Bw[bb], Bw[bb + 4]);
                        }
                    }
                }
            }
        }
    }

    // denominator (col 32 = ng==1, tile index 1, t==0)
    if (w < 12 && ng == 1 && t == 0) {
        den_s[mp * 16 + g] = acc[1][0];
        den_s[mp * 16 + g + 8] = acc[1][2];
    }
    __syncthreads();

    if (w < 12) {
        int b = bh >> 3, h = bh & 7;
#pragma unroll
        for (int mi = 0; mi < 2; mi++) {
            int rr = mp * 16 + g + mi * 8;
            int q = q0 + rr;
            if (q < SSZ) {
                float dinv = 1.f / den_s[rr];
                float* orow = out + ((size_t)b * SSZ + q) * EE + h * 32;
                if (ng == 0) {
#pragma unroll
                    for (int nt = 0; nt < 3; nt++) {
                        int col = nt * 8 + 2 * t;
                        orow[col]     = acc[nt][mi * 2]     * dinv;
                        orow[col + 1] = acc[nt][mi * 2 + 1] * dinv;
                    }
                } else {
                    int col = 24 + 2 * t;
                    orow[col]     = acc[0][mi * 2]     * dinv;
                    orow[col + 1] = acc[0][mi * 2 + 1] * dinv;
                }
            }
        }
    }
}

// ---------------------------------------------------------------------------
extern "C" void kernel_launch(void* const* d_in, const int* in_sizes, int n_in,
                              void* d_out, int out_size)
{
    const float* x  = (const float*)d_in[0];
    const float* Wq = (const float*)d_in[1];
    const float* bq = (const float*)d_in[2];
    const float* Wk = (const float*)d_in[3];
    const float* bk = (const float*)d_in[4];
    const float* Wv = (const float*)d_in[5];
    const float* bv = (const float*)d_in[6];
    float* out = (float*)d_out;

    {
        dim3 grid(12, 128);
        proj_kernel<<<grid, 256>>>(x, Wq, bq, Wk, bk, Wv, bv);
    }
    {
        const int total = NBH * KKEY * 32;
        vsum_kernel<<<(total + 255) / 256, 256>>>();
    }
    {
        cudaFuncSetAttribute(attn_kernel,
                             cudaFuncAttributeMaxDynamicSharedMemorySize,
                             SMEM_TOTAL);
        dim3 grid(NQT, NBH);
        attn_kernel<<<grid, NTH, SMEM_TOTAL>>>(out);
    }
}

// round 5
// speedup vs baseline: 1.7451x; 1.0955x over previous
#include <cuda_runtime.h>
#include <cuda_bf16.h>
#include <cstdint>

#define NBH   32
#define SSZ   2048
#define EE    256
#define HH    8
#define KKEY  2016
#define WWIN  33
#define TQ    96
#define NKT   21
#define NQT   22
#define NTH   512
#define NCHUNK 381
#define SCALE 0.17677669529663687f

#define QLD   104     // bf16 stride for QA/KB/P/V tiles (208 bytes)
#define GLD   132     // fp32 word stride for G

// smem byte offsets
#define OFF_TQQ  0
#define OFF_TKK  768
#define OFF_TLEN 1536
#define OFF_DEN  2304
#define OFF_QA   2688        // 128 x 208
#define OFF_KB0  29312       // 128 x 208
#define OFF_KB1  55936
#define OFF_G    82560       // 128 x 132 x 4
#define OFF_PH   150144      // 96 x 208
#define OFF_PL   170112
#define OFF_VH0  190080      // 40 x 208
#define OFF_VL0  198400
#define OFF_VH1  206720
#define OFF_VL1  215040
#define SMEM_TOTAL 223360

// device scratch (no runtime allocation allowed)
__device__ __align__(16) __nv_bfloat16 g_qA[(size_t)NBH * SSZ * 96];
__device__ __align__(16) __nv_bfloat16 g_kB[(size_t)NBH * SSZ * 96];
__device__ __align__(16) float         g_v [(size_t)NBH * SSZ * 32];
__device__ __align__(16) __nv_bfloat16 g_vsH[(size_t)NBH * 32 * KKEY];
__device__ __align__(16) __nv_bfloat16 g_vsL[(size_t)NBH * 32 * KKEY];

// ---------------- PTX helpers ----------------
__device__ __forceinline__ uint32_t smem_u32(const void* p) {
    uint32_t a;
    asm("{ .reg .u64 t; cvta.to.shared.u64 t, %1; cvt.u32.u64 %0, t; }"
        : "=r"(a) : "l"(p));
    return a;
}
__device__ __forceinline__ void mma16816(float* c, uint32_t a0, uint32_t a1,
                                         uint32_t a2, uint32_t a3,
                                         uint32_t b0, uint32_t b1)
{
    asm volatile(
        "mma.sync.aligned.m16n8k16.row.col.f32.bf16.bf16.f32 "
        "{%0,%1,%2,%3}, {%4,%5,%6,%7}, {%8,%9}, {%0,%1,%2,%3};"
        : "+f"(c[0]), "+f"(c[1]), "+f"(c[2]), "+f"(c[3])
        : "r"(a0), "r"(a1), "r"(a2), "r"(a3), "r"(b0), "r"(b1));
}
__device__ __forceinline__ void ldsm_x4(uint32_t addr, uint32_t& r0, uint32_t& r1,
                                        uint32_t& r2, uint32_t& r3)
{
    asm volatile("ldmatrix.sync.aligned.m8n8.x4.shared.b16 {%0,%1,%2,%3}, [%4];"
                 : "=r"(r0), "=r"(r1), "=r"(r2), "=r"(r3) : "r"(addr));
}
__device__ __forceinline__ void ldsm_x2(uint32_t addr, uint32_t& r0, uint32_t& r1)
{
    asm volatile("ldmatrix.sync.aligned.m8n8.x2.shared.b16 {%0,%1}, [%2];"
                 : "=r"(r0), "=r"(r1) : "r"(addr));
}
#define CP_ASYNC16(dst, src) \
    asm volatile("cp.async.cg.shared.global [%0], [%1], 16;" :: "r"(dst), "l"(src))
#define CP_COMMIT() asm volatile("cp.async.commit_group;" ::: "memory")
#define CP_WAIT0()  asm volatile("cp.async.wait_group 0;" ::: "memory")

// ---------------------------------------------------------------------------
// Kernel 1: QKV projection -> packed bf16-split layouts (96-wide rows)
// Q rows: [hi|lo|hi]   K rows: [hi|hi|lo]   V: fp32
// ---------------------------------------------------------------------------
__global__ __launch_bounds__(256) void proj_kernel(
    const float* __restrict__ x,
    const float* __restrict__ Wq, const float* __restrict__ bq,
    const float* __restrict__ Wk, const float* __restrict__ bk,
    const float* __restrict__ Wv, const float* __restrict__ bv)
{
    __shared__ float xs[64][17];
    __shared__ float ws[16][65];
    int tid = threadIdx.x;
    int m0 = blockIdx.y * 64;
    int n0 = blockIdx.x * 64;
    int msel = n0 >> 8;
    const float* Wsel = (msel == 0) ? Wq : (msel == 1) ? Wk : Wv;
    const float* bsel = (msel == 0) ? bq : (msel == 1) ? bk : bv;
    int ncol0 = n0 & 255;
    int ty = tid >> 4, tx = tid & 15;

    float acc[4][4];
#pragma unroll
    for (int i = 0; i < 4; i++)
#pragma unroll
        for (int j = 0; j < 4; j++) acc[i][j] = 0.f;

    for (int k0 = 0; k0 < EE; k0 += 16) {
        {
            int row = tid >> 2, kk = (tid & 3) * 4;
            float4 xv = *reinterpret_cast<const float4*>(
                &x[(size_t)(m0 + row) * EE + k0 + kk]);
            xs[row][kk] = xv.x; xs[row][kk + 1] = xv.y;
            xs[row][kk + 2] = xv.z; xs[row][kk + 3] = xv.w;
        }
        {
            int kk = tid >> 4, nn = (tid & 15) * 4;
            float4 wv = *reinterpret_cast<const float4*>(
                &Wsel[(size_t)(k0 + kk) * EE + ncol0 + nn]);
            ws[kk][nn] = wv.x; ws[kk][nn + 1] = wv.y;
            ws[kk][nn + 2] = wv.z; ws[kk][nn + 3] = wv.w;
        }
        __syncthreads();
#pragma unroll
        for (int kk = 0; kk < 16; kk++) {
            float a[4], b[4];
#pragma unroll
            for (int i = 0; i < 4; i++) a[i] = xs[ty * 4 + i][kk];
#pragma unroll
            for (int j = 0; j < 4; j++) b[j] = ws[kk][tx * 4 + j];
#pragma unroll
            for (int i = 0; i < 4; i++)
#pragma unroll
                for (int j = 0; j < 4; j++) acc[i][j] += a[i] * b[j];
        }
        __syncthreads();
    }

#pragma unroll
    for (int i = 0; i < 4; i++) {
        int m = m0 + ty * 4 + i;
        int b = m >> 11, s = m & 2047;
#pragma unroll
        for (int j = 0; j < 4; j++) {
            int e = ncol0 + tx * 4 + j;
            int h = e >> 5, d = e & 31;
            float val = acc[i][j] + bsel[e];
            if (msel == 2) {
                g_v[(((size_t)(b * HH + h) * SSZ + s) * 32) + d] = val;
            } else {
                __nv_bfloat16 hi = __float2bfloat16(val);
                __nv_bfloat16 lo = __float2bfloat16(val - __bfloat162float(hi));
                size_t rb = ((size_t)(b * HH + h) * SSZ + s) * 96;
                if (msel == 0) {
                    g_qA[rb + d] = hi;
                    g_qA[rb + 32 + d] = lo;
                    g_qA[rb + 64 + d] = hi;
                } else {
                    g_kB[rb + d] = hi;
                    g_kB[rb + 32 + d] = hi;
                    g_kB[rb + 64 + d] = lo;
                }
            }
        }
    }
}

// ---------------------------------------------------------------------------
// Kernel 2: transposed split sliding V-sums
// ---------------------------------------------------------------------------
__global__ void vsum_kernel()
{
    int idx = blockIdx.x * blockDim.x + threadIdx.x;
    const int total = NBH * KKEY * 32;
    if (idx >= total) return;
    int d = idx & 31;
    int k = (idx >> 5) % KKEY;
    int bh = idx / (32 * KKEY);
    const float* vp = &g_v[((size_t)bh * SSZ + k) * 32 + d];
    float s = 0.f;
#pragma unroll
    for (int w = 0; w < WWIN; w++) s += vp[w * 32];
    __nv_bfloat16 hi = __float2bfloat16(s);
    __nv_bfloat16 lo = __float2bfloat16(s - __bfloat162float(hi));
    size_t o = ((size_t)bh * 32 + d) * KKEY + k;
    g_vsH[o] = hi;
    g_vsL[o] = lo;
}

// ---------------------------------------------------------------------------
// Kernel 3: HMMA attention, ldmatrix operands, cp.async double-buffered K/V
// ---------------------------------------------------------------------------
__global__ __launch_bounds__(NTH, 1) void attn_kernel(float* __restrict__ out)
{
    extern __shared__ char sm[];
    uint32_t sb = smem_u32(sm);
    uint16_t* tqq  = (uint16_t*)(sm + OFF_TQQ);
    uint16_t* tkk  = (uint16_t*)(sm + OFF_TKK);
    uint16_t* tlen = (uint16_t*)(sm + OFF_TLEN);
    float* den_s = (float*)(sm + OFF_DEN);
    float* G = (float*)(sm + OFF_G);
    __nv_bfloat16* PH = (__nv_bfloat16*)(sm + OFF_PH);
    __nv_bfloat16* PL = (__nv_bfloat16*)(sm + OFF_PL);

    int tid = threadIdx.x;
    int w = tid >> 5, lane = tid & 31;
    int g = lane >> 2, t = lane & 3;
    int qt = blockIdx.x, bh = blockIdx.y;
    int q0 = qt * TQ;

    if (tid == 0) {           // diagonal chunk table
        int c = 0;
        for (int d = -95; d <= 95; d++) {
            int ad = d < 0 ? -d : d;
            int L = 96 - ad;
            int qs0 = d > 0 ? d : 0, ks0 = d > 0 ? 0 : -d;
            for (int t0 = 0; t0 < L; t0 += 32) {
                tqq[c] = (uint16_t)(qs0 + t0);
                tkk[c] = (uint16_t)(ks0 + t0);
                int l = L - t0; tlen[c] = (uint16_t)(l < 32 ? l : 32);
                c++;
            }
        }
    }

    // Q halo tile (rows q0-16 .. q0+111), zero-padded
    {
        const uint4* qsrc = (const uint4*)(g_qA + (size_t)bh * SSZ * 96);
        for (int idx = tid; idx < 128 * 12; idx += NTH) {
            int r = idx / 12, cb = idx % 12;
            int gq = q0 - 16 + r;
            uint4 v = make_uint4(0, 0, 0, 0);
            if (gq >= 0 && gq < SSZ) v = qsrc[(size_t)gq * 12 + cb];
            *(uint4*)(sm + OFF_QA + r * 208 + cb * 16) = v;
        }
    }
    // const V rows 32..39 for BOTH buffers; VH row32 = ones (denominator)
    for (int idx = tid; idx < 416; idx += NTH) {
        int buf = idx / 208, rem = idx % 208;
        int tt = rem / 104, r2 = rem % 104;
        int r = 32 + r2 / 13, cb = r2 % 13;
        uint4 v = make_uint4(0, 0, 0, 0);
        if (tt == 0 && r == 32)
            v = make_uint4(0x3F803F80u, 0x3F803F80u, 0x3F803F80u, 0x3F803F80u);
        int off = tt ? (buf ? OFF_VL1 : OFF_VL0) : (buf ? OFF_VH1 : OFF_VH0);
        *(uint4*)(sm + off + r * 208 + cb * 16) = v;
    }

    const uint4* ksrc = (const uint4*)(g_kB + (size_t)bh * SSZ * 96);

    // prologue: async-load tile 0 into buffer 0
    {
        for (int idx = tid; idx < 1536; idx += NTH) {
            int r = idx / 12, cb = idx % 12;
            CP_ASYNC16(sb + OFF_KB0 + r * 208 + cb * 16,
                       (const void*)(ksrc + (size_t)r * 12 + cb));
        }
        for (int idx = tid; idx < 768; idx += NTH) {
            int tt = idx / 384, rem = idx % 384;
            int d = rem / 12, cb = rem % 12;
            const __nv_bfloat16* src = (tt ? g_vsL : g_vsH)
                + ((size_t)bh * 32 + d) * KKEY + cb * 8;
            CP_ASYNC16(sb + (tt ? OFF_VL0 : OFF_VH0) + d * 208 + cb * 16,
                       (const void*)src);
        }
        CP_COMMIT();
    }

    // warp roles
    int mw = w >> 2, nw = w & 3;       // G: 4x4 warp grid, 32x32 tiles
    int r0 = mw * 32, kb = nw * 32;
    int mp = w >> 1, ng = w & 1;       // PV: warps 0..11
    int ntc = ng ? 2 : 3;

    // ldmatrix per-lane address components
    uint32_t aG0 = sb + OFF_QA + (uint32_t)(r0 + (lane & 15)) * 208 + (lane >> 4) * 16;
    uint32_t aG1 = aG0 + 16 * 208;
    uint32_t bRow = (uint32_t)(lane & 7) * 208 + ((lane >> 3) & 1) * 16;
    uint32_t aPH = sb + OFF_PH + (uint32_t)(mp * 16 + (lane & 15)) * 208 + (lane >> 4) * 16;
    uint32_t aPL = aPH + (OFF_PL - OFF_PH);

    float acc[3][4];
#pragma unroll
    for (int i = 0; i < 3; i++)
#pragma unroll
        for (int j = 0; j < 4; j++) acc[i][j] = 0.f;

    for (int kt = 0; kt < NKT; kt++) {
        int buf = kt & 1;
        CP_WAIT0();
        __syncthreads();

        // prefetch next tile into the other buffer
        if (kt + 1 < NKT) {
            int k0n = (kt + 1) * TQ;
            int obuf = buf ^ 1;
            for (int idx = tid; idx < 1536; idx += NTH) {
                int r = idx / 12, cb = idx % 12;
                CP_ASYNC16(sb + (obuf ? OFF_KB1 : OFF_KB0) + r * 208 + cb * 16,
                           (const void*)(ksrc + (size_t)(k0n + r) * 12 + cb));
            }
            for (int idx = tid; idx < 768; idx += NTH) {
                int tt = idx / 384, rem = idx % 384;
                int d = rem / 12, cb = rem % 12;
                const __nv_bfloat16* src = (tt ? g_vsL : g_vsH)
                    + ((size_t)bh * 32 + d) * KKEY + k0n + cb * 8;
                int off = tt ? (obuf ? OFF_VL1 : OFF_VL0)
                             : (obuf ? OFF_VH1 : OFF_VH0);
                CP_ASYNC16(sb + off + d * 208 + cb * 16, (const void*)src);
            }
            CP_COMMIT();
        }

        // --- G = QA @ KB^T  (M=128, N=128, K=96 packed split) ---
        {
            uint32_t kbase = sb + (buf ? OFF_KB1 : OFF_KB0) + bRow;
            float c[2][4][4];
#pragma unroll
            for (int mi = 0; mi < 2; mi++)
#pragma unroll
                for (int ni = 0; ni < 4; ni++)
#pragma unroll
                    for (int j = 0; j < 4; j++) c[mi][ni][j] = 0.f;
#pragma unroll
            for (int ks = 0; ks < 6; ks++) {
                uint32_t a0, a1, a2, a3, a4, a5, a6, a7;
                ldsm_x4(aG0 + ks * 32, a0, a1, a2, a3);
                ldsm_x4(aG1 + ks * 32, a4, a5, a6, a7);
#pragma unroll
                for (int ni = 0; ni < 4; ni++) {
                    uint32_t b0, b1;
                    ldsm_x2(kbase + (uint32_t)(kb + ni * 8) * 208 + ks * 32, b0, b1);
                    mma16816(c[0][ni], a0, a1, a2, a3, b0, b1);
                    mma16816(c[1][ni], a4, a5, a6, a7, b0, b1);
                }
            }
#pragma unroll
            for (int mi = 0; mi < 2; mi++)
#pragma unroll
                for (int ni = 0; ni < 4; ni++) {
                    int r = r0 + mi * 16 + g;
                    int col = kb + ni * 8 + 2 * t;
                    *(float2*)&G[r * GLD + col] =
                        make_float2(c[mi][ni][0], c[mi][ni][1]);
                    *(float2*)&G[(r + 8) * GLD + col] =
                        make_float2(c[mi][ni][2], c[mi][ni][3]);
                }
        }
        __syncthreads();

        // --- diagonal sliding-window scores + exp -> P split ---
        if (tid < NCHUNK) {
            int qq = tqq[tid], kk = tkk[tid], len = tlen[tid];
            float s = 0.f;
#pragma unroll
            for (int ww = 0; ww < WWIN; ww++)
                s += G[(qq + ww) * GLD + kk + ww];
            {
                float p = __expf(s * SCALE);
                __nv_bfloat16 hi = __float2bfloat16(p);
                __nv_bfloat16 lo = __float2bfloat16(p - __bfloat162float(hi));
                int off = qq * QLD + kk;
                PH[off] = hi;
                PL[off] = lo;
            }
#pragma unroll 4
            for (int u = 1; u < 32; u++) {
                int uu = (u < len) ? u : (len - 1);
                s += G[(qq + uu + 32) * GLD + (kk + uu + 32)]
                   - G[(qq + uu - 1) * GLD + (kk + uu - 1)];
                if (u < len) {
                    float p = __expf(s * SCALE);
                    __nv_bfloat16 hi = __float2bfloat16(p);
                    __nv_bfloat16 lo = __float2bfloat16(p - __bfloat162float(hi));
                    int off = (qq + u) * QLD + (kk + u);
                    PH[off] = hi;
                    PL[off] = lo;
                }
            }
        }
        __syncthreads();

        // --- PV accumulate: D += Phi@Vhi + Plo@Vhi + Phi@Vlo ---
        if (w < 12) {
            uint32_t vhb = sb + (buf ? OFF_VH1 : OFF_VH0) + bRow;
            uint32_t vlb = sb + (buf ? OFF_VL1 : OFF_VL0) + bRow;
#pragma unroll
            for (int pass = 0; pass < 3; pass++) {
                uint32_t Ab = (pass == 1) ? aPL : aPH;
                uint32_t Bb = (pass == 2) ? vlb : vhb;
#pragma unroll
                for (int ks = 0; ks < 6; ks++) {
                    uint32_t a0, a1, a2, a3;
                    ldsm_x4(Ab + ks * 32, a0, a1, a2, a3);
#pragma unroll
                    for (int nt = 0; nt < 3; nt++) {
                        if (nt < ntc) {
                            int tile = ng ? (3 + nt) : nt;
                            uint32_t b0, b1;
                            ldsm_x2(Bb + (uint32_t)(tile * 8) * 208 + ks * 32, b0, b1);
                            mma16816(acc[nt], a0, a1, a2, a3, b0, b1);
                        }
                    }
                }
            }
        }
    }

    // denominator (col 32 = ng==1, tile index 1, t==0)
    if (w < 12 && ng == 1 && t == 0) {
        den_s[mp * 16 + g] = acc[1][0];
        den_s[mp * 16 + g + 8] = acc[1][2];
    }
    __syncthreads();

    if (w < 12) {
        int b = bh >> 3, h = bh & 7;
#pragma unroll
        for (int mi = 0; mi < 2; mi++) {
            int rr = mp * 16 + g + mi * 8;
            int q = q0 + rr;
            if (q < SSZ) {
                float dinv = 1.f / den_s[rr];
                float* orow = out + ((size_t)b * SSZ + q) * EE + h * 32;
                if (ng == 0) {
#pragma unroll
                    for (int nt = 0; nt < 3; nt++) {
                        int col = nt * 8 + 2 * t;
                        orow[col]     = acc[nt][mi * 2]     * dinv;
                        orow[col + 1] = acc[nt][mi * 2 + 1] * dinv;
                    }
                } else {
                    int col = 24 + 2 * t;
                    orow[col]     = acc[0][mi * 2]     * dinv;
                    orow[col + 1] = acc[0][mi * 2 + 1] * dinv;
                }
            }
        }
    }
}

// ---------------------------------------------------------------------------
extern "C" void kernel_launch(void* const* d_in, const int* in_sizes, int n_in,
                              void* d_out, int out_size)
{
    const float* x  = (const float*)d_in[0];
    const float* Wq = (const float*)d_in[1];
    const float* bq = (const float*)d_in[2];
    const float* Wk = (const float*)d_in[3];
    const float* bk = (const float*)d_in[4];
    const float* Wv = (const float*)d_in[5];
    const float* bv = (const float*)d_in[6];
    float* out = (float*)d_out;

    {
        dim3 grid(12, 128);
        proj_kernel<<<grid, 256>>>(x, Wq, bq, Wk, bk, Wv, bv);
    }
    {
        const int total = NBH * KKEY * 32;
        vsum_kernel<<<(total + 255) / 256, 256>>>();
    }
    {
        cudaFuncSetAttribute(attn_kernel,
                             cudaFuncAttributeMaxDynamicSharedMemorySize,
                             SMEM_TOTAL);
        dim3 grid(NQT, NBH);
        attn_kernel<<<grid, NTH, SMEM_TOTAL>>>(out);
    }
}

// round 8
// speedup vs baseline: 1.7452x; 1.0001x over previous
#include <cuda_runtime.h>
#include <cuda_bf16.h>
#include <cstdint>

#define NBH   32
#define SSZ   2048
#define EE    256
#define HH    8
#define KKEY  2016
#define WWIN  33
#define TQ    96
#define NKT   21
#define NQT   22
#define NTH   512
#define NCHUNK 381
#define SCALE 0.17677669529663687f

#define QLD   104     // bf16 stride for QA/KB/P/V tiles (208 bytes)
#define GLD   132     // fp32 word stride for G

// smem byte offsets
#define OFF_TQQ  0
#define OFF_TKK  768
#define OFF_TLEN 1536
#define OFF_DEN  2304
#define OFF_QA   2688        // 128 x 208
#define OFF_KB0  29312       // 128 x 208
#define OFF_KB1  55936
#define OFF_G    82560       // 128 x 132 x 4
#define OFF_PH   150144      // 96 x 208
#define OFF_PL   170112
#define OFF_VH0  190080      // 40 x 208
#define OFF_VL0  198400
#define OFF_VH1  206720
#define OFF_VL1  215040
#define SMEM_TOTAL 223360

// device scratch (no runtime allocation allowed)
__device__ __align__(16) __nv_bfloat16 g_qA[(size_t)NBH * SSZ * 96];
__device__ __align__(16) __nv_bfloat16 g_kB[(size_t)NBH * SSZ * 96];
__device__ __align__(16) float         g_v [(size_t)NBH * SSZ * 32];
__device__ __align__(16) __nv_bfloat16 g_vsH[(size_t)NBH * 32 * KKEY];
__device__ __align__(16) __nv_bfloat16 g_vsL[(size_t)NBH * 32 * KKEY];

// ---------------- PTX helpers ----------------
__device__ __forceinline__ uint32_t smem_u32(const void* p) {
    uint32_t a;
    asm("{ .reg .u64 t; cvta.to.shared.u64 t, %1; cvt.u32.u64 %0, t; }"
        : "=r"(a) : "l"(p));
    return a;
}
__device__ __forceinline__ void mma16816(float* c, uint32_t a0, uint32_t a1,
                                         uint32_t a2, uint32_t a3,
                                         uint32_t b0, uint32_t b1)
{
    asm volatile(
        "mma.sync.aligned.m16n8k16.row.col.f32.bf16.bf16.f32 "
        "{%0,%1,%2,%3}, {%4,%5,%6,%7}, {%8,%9}, {%0,%1,%2,%3};"
        : "+f"(c[0]), "+f"(c[1]), "+f"(c[2]), "+f"(c[3])
        : "r"(a0), "r"(a1), "r"(a2), "r"(a3), "r"(b0), "r"(b1));
}
__device__ __forceinline__ void ldsm_x4(uint32_t addr, uint32_t& r0, uint32_t& r1,
                                        uint32_t& r2, uint32_t& r3)
{
    asm volatile("ldmatrix.sync.aligned.m8n8.x4.shared.b16 {%0,%1,%2,%3}, [%4];"
                 : "=r"(r0), "=r"(r1), "=r"(r2), "=r"(r3) : "r"(addr));
}
__device__ __forceinline__ void ldsm_x2(uint32_t addr, uint32_t& r0, uint32_t& r1)
{
    asm volatile("ldmatrix.sync.aligned.m8n8.x2.shared.b16 {%0,%1}, [%2];"
                 : "=r"(r0), "=r"(r1) : "r"(addr));
}
#define CP_ASYNC16(dst, src) \
    asm volatile("cp.async.cg.shared.global [%0], [%1], 16;" :: "r"(dst), "l"(src))
#define CP_COMMIT() asm volatile("cp.async.commit_group;" ::: "memory")
#define CP_WAIT0()  asm volatile("cp.async.wait_group 0;" ::: "memory")

// ---------------------------------------------------------------------------
// Kernel 1: QKV projection -> packed bf16-split layouts (96-wide rows)
// Q rows: [hi|lo|hi]   K rows: [hi|hi|lo]   V: fp32
// ---------------------------------------------------------------------------
__global__ __launch_bounds__(256) void proj_kernel(
    const float* __restrict__ x,
    const float* __restrict__ Wq, const float* __restrict__ bq,
    const float* __restrict__ Wk, const float* __restrict__ bk,
    const float* __restrict__ Wv, const float* __restrict__ bv)
{
    __shared__ float xs[64][17];
    __shared__ float ws[16][65];
    int tid = threadIdx.x;
    int m0 = blockIdx.y * 64;
    int n0 = blockIdx.x * 64;
    int msel = n0 >> 8;
    const float* Wsel = (msel == 0) ? Wq : (msel == 1) ? Wk : Wv;
    const float* bsel = (msel == 0) ? bq : (msel == 1) ? bk : bv;
    int ncol0 = n0 & 255;
    int ty = tid >> 4, tx = tid & 15;

    float acc[4][4];
#pragma unroll
    for (int i = 0; i < 4; i++)
#pragma unroll
        for (int j = 0; j < 4; j++) acc[i][j] = 0.f;

    for (int k0 = 0; k0 < EE; k0 += 16) {
        {
            int row = tid >> 2, kk = (tid & 3) * 4;
            float4 xv = *reinterpret_cast<const float4*>(
                &x[(size_t)(m0 + row) * EE + k0 + kk]);
            xs[row][kk] = xv.x; xs[row][kk + 1] = xv.y;
            xs[row][kk + 2] = xv.z; xs[row][kk + 3] = xv.w;
        }
        {
            int kk = tid >> 4, nn = (tid & 15) * 4;
            float4 wv = *reinterpret_cast<const float4*>(
                &Wsel[(size_t)(k0 + kk) * EE + ncol0 + nn]);
            ws[kk][nn] = wv.x; ws[kk][nn + 1] = wv.y;
            ws[kk][nn + 2] = wv.z; ws[kk][nn + 3] = wv.w;
        }
        __syncthreads();
#pragma unroll
        for (int kk = 0; kk < 16; kk++) {
            float a[4], b[4];
#pragma unroll
            for (int i = 0; i < 4; i++) a[i] = xs[ty * 4 + i][kk];
#pragma unroll
            for (int j = 0; j < 4; j++) b[j] = ws[kk][tx * 4 + j];
#pragma unroll
            for (int i = 0; i < 4; i++)
#pragma unroll
                for (int j = 0; j < 4; j++) acc[i][j] += a[i] * b[j];
        }
        __syncthreads();
    }

#pragma unroll
    for (int i = 0; i < 4; i++) {
        int m = m0 + ty * 4 + i;
        int b = m >> 11, s = m & 2047;
#pragma unroll
        for (int j = 0; j < 4; j++) {
            int e = ncol0 + tx * 4 + j;
            int h = e >> 5, d = e & 31;
            float val = acc[i][j] + bsel[e];
            if (msel == 2) {
                g_v[(((size_t)(b * HH + h) * SSZ + s) * 32) + d] = val;
            } else {
                __nv_bfloat16 hi = __float2bfloat16(val);
                __nv_bfloat16 lo = __float2bfloat16(val - __bfloat162float(hi));
                size_t rb = ((size_t)(b * HH + h) * SSZ + s) * 96;
                if (msel == 0) {
                    g_qA[rb + d] = hi;
                    g_qA[rb + 32 + d] = lo;
                    g_qA[rb + 64 + d] = hi;
                } else {
                    g_kB[rb + d] = hi;
                    g_kB[rb + 32 + d] = hi;
                    g_kB[rb + 64 + d] = lo;
                }
            }
        }
    }
}

// ---------------------------------------------------------------------------
// Kernel 2: transposed split sliding V-sums
// ---------------------------------------------------------------------------
__global__ void vsum_kernel()
{
    int idx = blockIdx.x * blockDim.x + threadIdx.x;
    const int total = NBH * KKEY * 32;
    if (idx >= total) return;
    int d = idx & 31;
    int k = (idx >> 5) % KKEY;
    int bh = idx / (32 * KKEY);
    const float* vp = &g_v[((size_t)bh * SSZ + k) * 32 + d];
    float s = 0.f;
#pragma unroll
    for (int w = 0; w < WWIN; w++) s += vp[w * 32];
    __nv_bfloat16 hi = __float2bfloat16(s);
    __nv_bfloat16 lo = __float2bfloat16(s - __bfloat162float(hi));
    size_t o = ((size_t)bh * 32 + d) * KKEY + k;
    g_vsH[o] = hi;
    g_vsL[o] = lo;
}

// ---------------------------------------------------------------------------
// Kernel 3: HMMA attention, ldmatrix operands, cp.async double-buffered K/V
// ---------------------------------------------------------------------------
__global__ __launch_bounds__(NTH, 1) void attn_kernel(float* __restrict__ out)
{
    extern __shared__ char sm[];
    uint32_t sb = smem_u32(sm);
    uint16_t* tqq  = (uint16_t*)(sm + OFF_TQQ);
    uint16_t* tkk  = (uint16_t*)(sm + OFF_TKK);
    uint16_t* tlen = (uint16_t*)(sm + OFF_TLEN);
    float* den_s = (float*)(sm + OFF_DEN);
    float* G = (float*)(sm + OFF_G);
    __nv_bfloat16* PH = (__nv_bfloat16*)(sm + OFF_PH);
    __nv_bfloat16* PL = (__nv_bfloat16*)(sm + OFF_PL);

    int tid = threadIdx.x;
    int w = tid >> 5, lane = tid & 31;
    int g = lane >> 2, t = lane & 3;
    int qt = blockIdx.x, bh = blockIdx.y;
    int q0 = qt * TQ;

    if (tid == 0) {           // diagonal chunk table
        int c = 0;
        for (int d = -95; d <= 95; d++) {
            int ad = d < 0 ? -d : d;
            int L = 96 - ad;
            int qs0 = d > 0 ? d : 0, ks0 = d > 0 ? 0 : -d;
            for (int t0 = 0; t0 < L; t0 += 32) {
                tqq[c] = (uint16_t)(qs0 + t0);
                tkk[c] = (uint16_t)(ks0 + t0);
                int l = L - t0; tlen[c] = (uint16_t)(l < 32 ? l : 32);
                c++;
            }
        }
    }

    // Q halo tile (rows q0-16 .. q0+111), zero-padded
    {
        const uint4* qsrc = (const uint4*)(g_qA + (size_t)bh * SSZ * 96);
        for (int idx = tid; idx < 128 * 12; idx += NTH) {
            int r = idx / 12, cb = idx % 12;
            int gq = q0 - 16 + r;
            uint4 v = make_uint4(0, 0, 0, 0);
            if (gq >= 0 && gq < SSZ) v = qsrc[(size_t)gq * 12 + cb];
            *(uint4*)(sm + OFF_QA + r * 208 + cb * 16) = v;
        }
    }
    // const V rows 32..39 for BOTH buffers; VH row32 = ones (denominator)
    for (int idx = tid; idx < 416; idx += NTH) {
        int buf = idx / 208, rem = idx % 208;
        int tt = rem / 104, r2 = rem % 104;
        int r = 32 + r2 / 13, cb = r2 % 13;
        uint4 v = make_uint4(0, 0, 0, 0);
        if (tt == 0 && r == 32)
            v = make_uint4(0x3F803F80u, 0x3F803F80u, 0x3F803F80u, 0x3F803F80u);
        int off = tt ? (buf ? OFF_VL1 : OFF_VL0) : (buf ? OFF_VH1 : OFF_VH0);
        *(uint4*)(sm + off + r * 208 + cb * 16) = v;
    }

    const uint4* ksrc = (const uint4*)(g_kB + (size_t)bh * SSZ * 96);

    // prologue: async-load tile 0 into buffer 0
    {
        for (int idx = tid; idx < 1536; idx += NTH) {
            int r = idx / 12, cb = idx % 12;
            CP_ASYNC16(sb + OFF_KB0 + r * 208 + cb * 16,
                       (const void*)(ksrc + (size_t)r * 12 + cb));
        }
        for (int idx = tid; idx < 768; idx += NTH) {
            int tt = idx / 384, rem = idx % 384;
            int d = rem / 12, cb = rem % 12;
            const __nv_bfloat16* src = (tt ? g_vsL : g_vsH)
                + ((size_t)bh * 32 + d) * KKEY + cb * 8;
            CP_ASYNC16(sb + (tt ? OFF_VL0 : OFF_VH0) + d * 208 + cb * 16,
                       (const void*)src);
        }
        CP_COMMIT();
    }

    // warp roles
    int mw = w >> 2, nw = w & 3;       // G: 4x4 warp grid, 32x32 tiles
    int r0 = mw * 32, kb = nw * 32;
    int mp = w >> 1, ng = w & 1;       // PV: warps 0..11
    int ntc = ng ? 2 : 3;

    // ldmatrix per-lane address components
    uint32_t aG0 = sb + OFF_QA + (uint32_t)(r0 + (lane & 15)) * 208 + (lane >> 4) * 16;
    uint32_t aG1 = aG0 + 16 * 208;
    uint32_t bRow = (uint32_t)(lane & 7) * 208 + ((lane >> 3) & 1) * 16;
    uint32_t aPH = sb + OFF_PH + (uint32_t)(mp * 16 + (lane & 15)) * 208 + (lane >> 4) * 16;
    uint32_t aPL = aPH + (OFF_PL - OFF_PH);

    float acc[3][4];
#pragma unroll
    for (int i = 0; i < 3; i++)
#pragma unroll
        for (int j = 0; j < 4; j++) acc[i][j] = 0.f;

    for (int kt = 0; kt < NKT; kt++) {
        int buf = kt & 1;
        CP_WAIT0();
        __syncthreads();

        // prefetch next tile into the other buffer
        if (kt + 1 < NKT) {
            int k0n = (kt + 1) * TQ;
            int obuf = buf ^ 1;
            for (int idx = tid; idx < 1536; idx += NTH) {
                int r = idx / 12, cb = idx % 12;
                CP_ASYNC16(sb + (obuf ? OFF_KB1 : OFF_KB0) + r * 208 + cb * 16,
                           (const void*)(ksrc + (size_t)(k0n + r) * 12 + cb));
            }
            for (int idx = tid; idx < 768; idx += NTH) {
                int tt = idx / 384, rem = idx % 384;
                int d = rem / 12, cb = rem % 12;
                const __nv_bfloat16* src = (tt ? g_vsL : g_vsH)
                    + ((size_t)bh * 32 + d) * KKEY + k0n + cb * 8;
                int off = tt ? (obuf ? OFF_VL1 : OFF_VL0)
                             : (obuf ? OFF_VH1 : OFF_VH0);
                CP_ASYNC16(sb + off + d * 208 + cb * 16, (const void*)src);
            }
            CP_COMMIT();
        }

        // --- G = QA @ KB^T  (M=128, N=128, K=96 packed split) ---
        {
            uint32_t kbase = sb + (buf ? OFF_KB1 : OFF_KB0) + bRow;
            float c[2][4][4];
#pragma unroll
            for (int mi = 0; mi < 2; mi++)
#pragma unroll
                for (int ni = 0; ni < 4; ni++)
#pragma unroll
                    for (int j = 0; j < 4; j++) c[mi][ni][j] = 0.f;
#pragma unroll
            for (int ks = 0; ks < 6; ks++) {
                uint32_t a0, a1, a2, a3, a4, a5, a6, a7;
                ldsm_x4(aG0 + ks * 32, a0, a1, a2, a3);
                ldsm_x4(aG1 + ks * 32, a4, a5, a6, a7);
#pragma unroll
                for (int ni = 0; ni < 4; ni++) {
                    uint32_t b0, b1;
                    ldsm_x2(kbase + (uint32_t)(kb + ni * 8) * 208 + ks * 32, b0, b1);
                    mma16816(c[0][ni], a0, a1, a2, a3, b0, b1);
                    mma16816(c[1][ni], a4, a5, a6, a7, b0, b1);
                }
            }
#pragma unroll
            for (int mi = 0; mi < 2; mi++)
#pragma unroll
                for (int ni = 0; ni < 4; ni++) {
                    int r = r0 + mi * 16 + g;
                    int col = kb + ni * 8 + 2 * t;
                    *(float2*)&G[r * GLD + col] =
                        make_float2(c[mi][ni][0], c[mi][ni][1]);
                    *(float2*)&G[(r + 8) * GLD + col] =
                        make_float2(c[mi][ni][2], c[mi][ni][3]);
                }
        }
        __syncthreads();

        // --- diagonal sliding-window scores + exp -> P split ---
        if (tid < NCHUNK) {
            int qq = tqq[tid], kk = tkk[tid], len = tlen[tid];
            float s = 0.f;
#pragma unroll
            for (int ww = 0; ww < WWIN; ww++)
                s += G[(qq + ww) * GLD + kk + ww];
            {
                float p = __expf(s * SCALE);
                __nv_bfloat16 hi = __float2bfloat16(p);
                __nv_bfloat16 lo = __float2bfloat16(p - __bfloat162float(hi));
                int off = qq * QLD + kk;
                PH[off] = hi;
                PL[off] = lo;
            }
#pragma unroll 4
            for (int u = 1; u < 32; u++) {
                int uu = (u < len) ? u : (len - 1);
                s += G[(qq + uu + 32) * GLD + (kk + uu + 32)]
                   - G[(qq + uu - 1) * GLD + (kk + uu - 1)];
                if (u < len) {
                    float p = __expf(s * SCALE);
                    __nv_bfloat16 hi = __float2bfloat16(p);
                    __nv_bfloat16 lo = __float2bfloat16(p - __bfloat162float(hi));
                    int off = (qq + u) * QLD + (kk + u);
                    PH[off] = hi;
                    PL[off] = lo;
                }
            }
        }
        __syncthreads();

        // --- PV accumulate: D += Phi@Vhi + Plo@Vhi + Phi@Vlo ---
        if (w < 12) {
            uint32_t vhb = sb + (buf ? OFF_VH1 : OFF_VH0) + bRow;
            uint32_t vlb = sb + (buf ? OFF_VL1 : OFF_VL0) + bRow;
#pragma unroll
            for (int pass = 0; pass < 3; pass++) {
                uint32_t Ab = (pass == 1) ? aPL : aPH;
                uint32_t Bb = (pass == 2) ? vlb : vhb;
#pragma unroll
                for (int ks = 0; ks < 6; ks++) {
                    uint32_t a0, a1, a2, a3;
                    ldsm_x4(Ab + ks * 32, a0, a1, a2, a3);
#pragma unroll
                    for (int nt = 0; nt < 3; nt++) {
                        if (nt < ntc) {
                            int tile = ng ? (3 + nt) : nt;
                            uint32_t b0, b1;
                            ldsm_x2(Bb + (uint32_t)(tile * 8) * 208 + ks * 32, b0, b1);
                            mma16816(acc[nt], a0, a1, a2, a3, b0, b1);
                        }
                    }
                }
            }
        }
    }

    // denominator (col 32 = ng==1, tile index 1, t==0)
    if (w < 12 && ng == 1 && t == 0) {
        den_s[mp * 16 + g] = acc[1][0];
        den_s[mp * 16 + g + 8] = acc[1][2];
    }
    __syncthreads();

    if (w < 12) {
        int b = bh >> 3, h = bh & 7;
#pragma unroll
        for (int mi = 0; mi < 2; mi++) {
            int rr = mp * 16 + g + mi * 8;
            int q = q0 + rr;
            if (q < SSZ) {
                float dinv = 1.f / den_s[rr];
                float* orow = out + ((size_t)b * SSZ + q) * EE + h * 32;
                if (ng == 0) {
#pragma unroll
                    for (int nt = 0; nt < 3; nt++) {
                        int col = nt * 8 + 2 * t;
                        orow[col]     = acc[nt][mi * 2]     * dinv;
                        orow[col + 1] = acc[nt][mi * 2 + 1] * dinv;
                    }
                } else {
                    int col = 24 + 2 * t;
                    orow[col]     = acc[0][mi * 2]     * dinv;
                    orow[col + 1] = acc[0][mi * 2 + 1] * dinv;
                }
            }
        }
    }
}

// ---------------------------------------------------------------------------
extern "C" void kernel_launch(void* const* d_in, const int* in_sizes, int n_in,
                              void* d_out, int out_size)
{
    const float* x  = (const float*)d_in[0];
    const float* Wq = (const float*)d_in[1];
    const float* bq = (const float*)d_in[2];
    const float* Wk = (const float*)d_in[3];
    const float* bk = (const float*)d_in[4];
    const float* Wv = (const float*)d_in[5];
    const float* bv = (const float*)d_in[6];
    float* out = (float*)d_out;

    {
        dim3 grid(12, 128);
        proj_kernel<<<grid, 256>>>(x, Wq, bq, Wk, bk, Wv, bv);
    }
    {
        const int total = NBH * KKEY * 32;
        vsum_kernel<<<(total + 255) / 256, 256>>>();
    }
    {
        cudaFuncSetAttribute(attn_kernel,
                             cudaFuncAttributeMaxDynamicSharedMemorySize,
                             SMEM_TOTAL);
        dim3 grid(NQT, NBH);
        attn_kernel<<<grid, NTH, SMEM_TOTAL>>>(out);
    }
}

// round 9
// speedup vs baseline: 1.9594x; 1.1227x over previous
#include <cuda_runtime.h>
#include <cuda_bf16.h>
#include <cstdint>

#define NBH   32
#define SSZ   2048
#define EE    256
#define HH    8
#define KKEY  2016
#define WWIN  33
#define TQ    96
#define NKT   21
#define NQT   22
#define NTH   512
#define NCHUNK 381
#define SCALE 0.17677669529663687f

#define QLD   104     // bf16 stride for QA/KB/P/V tiles (208 bytes)
#define GLD   131     // fp32 word stride for G (odd -> conflict-free diag reads)

// smem byte offsets
#define OFF_TQQ  0
#define OFF_TKK  768
#define OFF_TLEN 1536
#define OFF_DEN  2304
#define OFF_QA   2688        // 128 x 208
#define OFF_KB0  29312       // 128 x 208
#define OFF_KB1  55936
#define OFF_G    82560       // 128 x 131 x 4 = 67072
#define OFF_PH   149632      // 96 x 208
#define OFF_PL   169600
#define OFF_VH0  189568      // 40 x 208
#define OFF_VL0  197888
#define OFF_VH1  206208
#define OFF_VL1  214528
#define SMEM_TOTAL 222848

// device scratch (no runtime allocation allowed)
__device__ __align__(16) __nv_bfloat16 g_qA[(size_t)NBH * SSZ * 96];
__device__ __align__(16) __nv_bfloat16 g_kB[(size_t)NBH * SSZ * 96];
__device__ __align__(16) float         g_v [(size_t)NBH * SSZ * 32];
__device__ __align__(16) __nv_bfloat16 g_vsH[(size_t)NBH * 32 * KKEY];
__device__ __align__(16) __nv_bfloat16 g_vsL[(size_t)NBH * 32 * KKEY];

// ---------------- PTX helpers ----------------
__device__ __forceinline__ uint32_t smem_u32(const void* p) {
    uint32_t a;
    asm("{ .reg .u64 t; cvta.to.shared.u64 t, %1; cvt.u32.u64 %0, t; }"
        : "=r"(a) : "l"(p));
    return a;
}
__device__ __forceinline__ void mma16816(float* c, uint32_t a0, uint32_t a1,
                                         uint32_t a2, uint32_t a3,
                                         uint32_t b0, uint32_t b1)
{
    asm volatile(
        "mma.sync.aligned.m16n8k16.row.col.f32.bf16.bf16.f32 "
        "{%0,%1,%2,%3}, {%4,%5,%6,%7}, {%8,%9}, {%0,%1,%2,%3};"
        : "+f"(c[0]), "+f"(c[1]), "+f"(c[2]), "+f"(c[3])
        : "r"(a0), "r"(a1), "r"(a2), "r"(a3), "r"(b0), "r"(b1));
}
__device__ __forceinline__ void ldsm_x4(uint32_t addr, uint32_t& r0, uint32_t& r1,
                                        uint32_t& r2, uint32_t& r3)
{
    asm volatile("ldmatrix.sync.aligned.m8n8.x4.shared.b16 {%0,%1,%2,%3}, [%4];"
                 : "=r"(r0), "=r"(r1), "=r"(r2), "=r"(r3) : "r"(addr));
}
__device__ __forceinline__ void ldsm_x2(uint32_t addr, uint32_t& r0, uint32_t& r1)
{
    asm volatile("ldmatrix.sync.aligned.m8n8.x2.shared.b16 {%0,%1}, [%2];"
                 : "=r"(r0), "=r"(r1) : "r"(addr));
}
#define CP_ASYNC16(dst, src) \
    asm volatile("cp.async.cg.shared.global [%0], [%1], 16;" :: "r"(dst), "l"(src))
#define CP_COMMIT() asm volatile("cp.async.commit_group;" ::: "memory")
#define CP_WAIT0()  asm volatile("cp.async.wait_group 0;" ::: "memory")

// ---------------------------------------------------------------------------
// Kernel 1: QKV projection -> packed bf16-split layouts (96-wide rows)
// Q rows: [hi|lo|hi]   K rows: [hi|hi|lo]   V: fp32
// xs transposed [kk][row] so both MMA operands use float4 LDS.
// ---------------------------------------------------------------------------
__global__ __launch_bounds__(256) void proj_kernel(
    const float* __restrict__ x,
    const float* __restrict__ Wq, const float* __restrict__ bq,
    const float* __restrict__ Wk, const float* __restrict__ bk,
    const float* __restrict__ Wv, const float* __restrict__ bv)
{
    __shared__ float xs[16][68];    // [kk][row]
    __shared__ float ws[16][68];
    int tid = threadIdx.x;
    int m0 = blockIdx.y * 64;
    int n0 = blockIdx.x * 64;
    int msel = n0 >> 8;
    const float* Wsel = (msel == 0) ? Wq : (msel == 1) ? Wk : Wv;
    const float* bsel = (msel == 0) ? bq : (msel == 1) ? bk : bv;
    int ncol0 = n0 & 255;
    int ty = tid >> 4, tx = tid & 15;

    float acc[4][4];
#pragma unroll
    for (int i = 0; i < 4; i++)
#pragma unroll
        for (int j = 0; j < 4; j++) acc[i][j] = 0.f;

    for (int k0 = 0; k0 < EE; k0 += 16) {
        {   // x tile 64x16 -> transposed smem
            int row = tid >> 2, kk = (tid & 3) * 4;
            float4 xv = *reinterpret_cast<const float4*>(
                &x[(size_t)(m0 + row) * EE + k0 + kk]);
            xs[kk][row]     = xv.x; xs[kk + 1][row] = xv.y;
            xs[kk + 2][row] = xv.z; xs[kk + 3][row] = xv.w;
        }
        {   // W tile 16x64
            int kk = tid >> 4, nn = (tid & 15) * 4;
            float4 wv = *reinterpret_cast<const float4*>(
                &Wsel[(size_t)(k0 + kk) * EE + ncol0 + nn]);
            *(float4*)&ws[kk][nn] = wv;
        }
        __syncthreads();
#pragma unroll
        for (int kk = 0; kk < 16; kk++) {
            float4 a4 = *(const float4*)&xs[kk][ty * 4];
            float4 b4 = *(const float4*)&ws[kk][tx * 4];
            float a[4] = {a4.x, a4.y, a4.z, a4.w};
            float b[4] = {b4.x, b4.y, b4.z, b4.w};
#pragma unroll
            for (int i = 0; i < 4; i++)
#pragma unroll
                for (int j = 0; j < 4; j++) acc[i][j] += a[i] * b[j];
        }
        __syncthreads();
    }

#pragma unroll
    for (int i = 0; i < 4; i++) {
        int m = m0 + ty * 4 + i;
        int b = m >> 11, s = m & 2047;
#pragma unroll
        for (int j = 0; j < 4; j++) {
            int e = ncol0 + tx * 4 + j;
            int h = e >> 5, d = e & 31;
            float val = acc[i][j] + bsel[e];
            if (msel == 2) {
                g_v[(((size_t)(b * HH + h) * SSZ + s) * 32) + d] = val;
            } else {
                __nv_bfloat16 hi = __float2bfloat16(val);
                __nv_bfloat16 lo = __float2bfloat16(val - __bfloat162float(hi));
                size_t rb = ((size_t)(b * HH + h) * SSZ + s) * 96;
                if (msel == 0) {
                    g_qA[rb + d] = hi;
                    g_qA[rb + 32 + d] = lo;
                    g_qA[rb + 64 + d] = hi;
                } else {
                    g_kB[rb + d] = hi;
                    g_kB[rb + 32 + d] = hi;
                    g_kB[rb + 64 + d] = lo;
                }
            }
        }
    }
}

// ---------------------------------------------------------------------------
// Kernel 2: transposed split sliding V-sums
// ---------------------------------------------------------------------------
__global__ void vsum_kernel()
{
    int idx = blockIdx.x * blockDim.x + threadIdx.x;
    const int total = NBH * KKEY * 32;
    if (idx >= total) return;
    int d = idx & 31;
    int k = (idx >> 5) % KKEY;
    int bh = idx / (32 * KKEY);
    const float* vp = &g_v[((size_t)bh * SSZ + k) * 32 + d];
    float s = 0.f;
#pragma unroll
    for (int w = 0; w < WWIN; w++) s += vp[w * 32];
    __nv_bfloat16 hi = __float2bfloat16(s);
    __nv_bfloat16 lo = __float2bfloat16(s - __bfloat162float(hi));
    size_t o = ((size_t)bh * 32 + d) * KKEY + k;
    g_vsH[o] = hi;
    g_vsL[o] = lo;
}

// ---------------------------------------------------------------------------
// Kernel 3: HMMA attention; chunk table t0-major (conflict-free diag reads)
// ---------------------------------------------------------------------------
__global__ __launch_bounds__(NTH, 1) void attn_kernel(float* __restrict__ out)
{
    extern __shared__ char sm[];
    uint32_t sb = smem_u32(sm);
    uint16_t* tqq  = (uint16_t*)(sm + OFF_TQQ);
    uint16_t* tkk  = (uint16_t*)(sm + OFF_TKK);
    uint16_t* tlen = (uint16_t*)(sm + OFF_TLEN);
    float* den_s = (float*)(sm + OFF_DEN);
    float* G = (float*)(sm + OFF_G);
    __nv_bfloat16* PH = (__nv_bfloat16*)(sm + OFF_PH);
    __nv_bfloat16* PL = (__nv_bfloat16*)(sm + OFF_PL);

    int tid = threadIdx.x;
    int w = tid >> 5, lane = tid & 31;
    int g = lane >> 2, t = lane & 3;
    int qt = blockIdx.x, bh = blockIdx.y;
    int q0 = qt * TQ;

    if (tid == 0) {
        // chunk table, t0-major: warp lanes land on ADJACENT diagonals ->
        // addr deltas of 1 (k-side) or GLD=131 (q-side), conflict-free.
        int c = 0;
        for (int t0 = 0; t0 < TQ; t0 += 32) {
            for (int d = -95; d <= 95; d++) {
                int ad = d < 0 ? -d : d;
                int L = 96 - ad;
                if (t0 >= L) continue;
                int qs0 = d > 0 ? d : 0, ks0 = d > 0 ? 0 : -d;
                tqq[c] = (uint16_t)(qs0 + t0);
                tkk[c] = (uint16_t)(ks0 + t0);
                int l = L - t0; tlen[c] = (uint16_t)(l < 32 ? l : 32);
                c++;
            }
        }
    }

    // Q halo tile (rows q0-16 .. q0+111), zero-padded
    {
        const uint4* qsrc = (const uint4*)(g_qA + (size_t)bh * SSZ * 96);
        for (int idx = tid; idx < 128 * 12; idx += NTH) {
            int r = idx / 12, cb = idx % 12;
            int gq = q0 - 16 + r;
            uint4 v = make_uint4(0, 0, 0, 0);
            if (gq >= 0 && gq < SSZ) v = qsrc[(size_t)gq * 12 + cb];
            *(uint4*)(sm + OFF_QA + r * 208 + cb * 16) = v;
        }
    }
    // const V rows 32..39 for BOTH buffers; VH row32 = ones (denominator)
    for (int idx = tid; idx < 416; idx += NTH) {
        int buf = idx / 208, rem = idx % 208;
        int tt = rem / 104, r2 = rem % 104;
        int r = 32 + r2 / 13, cb = r2 % 13;
        uint4 v = make_uint4(0, 0, 0, 0);
        if (tt == 0 && r == 32)
            v = make_uint4(0x3F803F80u, 0x3F803F80u, 0x3F803F80u, 0x3F803F80u);
        int off = tt ? (buf ? OFF_VL1 : OFF_VL0) : (buf ? OFF_VH1 : OFF_VH0);
        *(uint4*)(sm + off + r * 208 + cb * 16) = v;
    }

    const uint4* ksrc = (const uint4*)(g_kB + (size_t)bh * SSZ * 96);

    // prologue: async-load tile 0 into buffer 0
    {
        for (int idx = tid; idx < 1536; idx += NTH) {
            int r = idx / 12, cb = idx % 12;
            CP_ASYNC16(sb + OFF_KB0 + r * 208 + cb * 16,
                       (const void*)(ksrc + (size_t)r * 12 + cb));
        }
        for (int idx = tid; idx < 768; idx += NTH) {
            int tt = idx / 384, rem = idx % 384;
            int d = rem / 12, cb = rem % 12;
            const __nv_bfloat16* src = (tt ? g_vsL : g_vsH)
                + ((size_t)bh * 32 + d) * KKEY + cb * 8;
            CP_ASYNC16(sb + (tt ? OFF_VL0 : OFF_VH0) + d * 208 + cb * 16,
                       (const void*)src);
        }
        CP_COMMIT();
    }

    // warp roles
    int mw = w >> 2, nw = w & 3;       // G: 4x4 warp grid, 32x32 tiles
    int r0 = mw * 32, kb = nw * 32;
    int mp = w >> 1, ng = w & 1;       // PV: warps 0..11

    // ldmatrix per-lane address components
    uint32_t aG0 = sb + OFF_QA + (uint32_t)(r0 + (lane & 15)) * 208 + (lane >> 4) * 16;
    uint32_t aG1 = aG0 + 16 * 208;
    // x4 B pattern: lane -> (ntile = lane>>4, kchunk = (lane>>3)&1, row = lane&7)
    uint32_t bRow4 = ((uint32_t)(lane >> 4) * 8 + (lane & 7)) * 208
                   + ((lane >> 3) & 1) * 16;
    uint32_t bRow2 = (uint32_t)(lane & 7) * 208 + ((lane >> 3) & 1) * 16;
    uint32_t aPH = sb + OFF_PH + (uint32_t)(mp * 16 + (lane & 15)) * 208 + (lane >> 4) * 16;
    uint32_t aPL = aPH + (OFF_PL - OFF_PH);

    float acc[3][4];
#pragma unroll
    for (int i = 0; i < 3; i++)
#pragma unroll
        for (int j = 0; j < 4; j++) acc[i][j] = 0.f;

    for (int kt = 0; kt < NKT; kt++) {
        int buf = kt & 1;
        CP_WAIT0();
        __syncthreads();

        // prefetch next tile into the other buffer
        if (kt + 1 < NKT) {
            int k0n = (kt + 1) * TQ;
            int obuf = buf ^ 1;
            for (int idx = tid; idx < 1536; idx += NTH) {
                int r = idx / 12, cb = idx % 12;
                CP_ASYNC16(sb + (obuf ? OFF_KB1 : OFF_KB0) + r * 208 + cb * 16,
                           (const void*)(ksrc + (size_t)(k0n + r) * 12 + cb));
            }
            for (int idx = tid; idx < 768; idx += NTH) {
                int tt = idx / 384, rem = idx % 384;
                int d = rem / 12, cb = rem % 12;
                const __nv_bfloat16* src = (tt ? g_vsL : g_vsH)
                    + ((size_t)bh * 32 + d) * KKEY + k0n + cb * 8;
                int off = tt ? (obuf ? OFF_VL1 : OFF_VL0)
                             : (obuf ? OFF_VH1 : OFF_VH0);
                CP_ASYNC16(sb + off + d * 208 + cb * 16, (const void*)src);
            }
            CP_COMMIT();
        }

        // --- G = QA @ KB^T  (M=128, N=128, K=96 packed split) ---
        {
            uint32_t kbase = sb + (buf ? OFF_KB1 : OFF_KB0);
            float c[2][4][4];
#pragma unroll
            for (int mi = 0; mi < 2; mi++)
#pragma unroll
                for (int ni = 0; ni < 4; ni++)
#pragma unroll
                    for (int j = 0; j < 4; j++) c[mi][ni][j] = 0.f;
#pragma unroll
            for (int ks = 0; ks < 6; ks++) {
                uint32_t a0, a1, a2, a3, a4, a5, a6, a7;
                ldsm_x4(aG0 + ks * 32, a0, a1, a2, a3);
                ldsm_x4(aG1 + ks * 32, a4, a5, a6, a7);
#pragma unroll
                for (int p = 0; p < 2; p++) {
                    uint32_t b0, b1, b2, b3;
                    ldsm_x4(kbase + (uint32_t)(kb + p * 16) * 208 + bRow4 + ks * 32,
                            b0, b1, b2, b3);
                    mma16816(c[0][2 * p],     a0, a1, a2, a3, b0, b1);
                    mma16816(c[1][2 * p],     a4, a5, a6, a7, b0, b1);
                    mma16816(c[0][2 * p + 1], a0, a1, a2, a3, b2, b3);
                    mma16816(c[1][2 * p + 1], a4, a5, a6, a7, b2, b3);
                }
            }
#pragma unroll
            for (int mi = 0; mi < 2; mi++)
#pragma unroll
                for (int ni = 0; ni < 4; ni++) {
                    int r = r0 + mi * 16 + g;
                    int col = kb + ni * 8 + 2 * t;
                    G[r * GLD + col]            = c[mi][ni][0];
                    G[r * GLD + col + 1]        = c[mi][ni][1];
                    G[(r + 8) * GLD + col]      = c[mi][ni][2];
                    G[(r + 8) * GLD + col + 1]  = c[mi][ni][3];
                }
        }
        __syncthreads();

        // --- diagonal sliding-window scores + exp -> P split ---
        if (tid < NCHUNK) {
            int qq = tqq[tid], kk = tkk[tid], len = tlen[tid];
            float s = 0.f;
#pragma unroll
            for (int ww = 0; ww < WWIN; ww++)
                s += G[(qq + ww) * GLD + kk + ww];
            {
                float p = __expf(s * SCALE);
                __nv_bfloat16 hi = __float2bfloat16(p);
                __nv_bfloat16 lo = __float2bfloat16(p - __bfloat162float(hi));
                int off = qq * QLD + kk;
                PH[off] = hi;
                PL[off] = lo;
            }
#pragma unroll 4
            for (int u = 1; u < 32; u++) {
                int uu = (u < len) ? u : (len - 1);
                s += G[(qq + uu + 32) * GLD + (kk + uu + 32)]
                   - G[(qq + uu - 1) * GLD + (kk + uu - 1)];
                if (u < len) {
                    float p = __expf(s * SCALE);
                    __nv_bfloat16 hi = __float2bfloat16(p);
                    __nv_bfloat16 lo = __float2bfloat16(p - __bfloat162float(hi));
                    int off = (qq + u) * QLD + (kk + u);
                    PH[off] = hi;
                    PL[off] = lo;
                }
            }
        }
        __syncthreads();

        // --- PV accumulate: D += Phi@Vhi + Plo@Vhi + Phi@Vlo ---
        if (w < 12) {
            uint32_t vhb = sb + (buf ? OFF_VH1 : OFF_VH0);
            uint32_t vlb = sb + (buf ? OFF_VL1 : OFF_VL0);
#pragma unroll
            for (int pass = 0; pass < 3; pass++) {
                uint32_t Ab = (pass == 1) ? aPL : aPH;
                uint32_t Bb = (pass == 2) ? vlb : vhb;
#pragma unroll
                for (int ks = 0; ks < 6; ks++) {
                    uint32_t a0, a1, a2, a3;
                    ldsm_x4(Ab + ks * 32, a0, a1, a2, a3);
                    if (ng == 0) {
                        uint32_t b0, b1, b2, b3;
                        ldsm_x4(Bb + bRow4 + ks * 32, b0, b1, b2, b3);
                        mma16816(acc[0], a0, a1, a2, a3, b0, b1);
                        mma16816(acc[1], a0, a1, a2, a3, b2, b3);
                        uint32_t c0, c1;
                        ldsm_x2(Bb + 16 * 208 + bRow2 + ks * 32, c0, c1);
                        mma16816(acc[2], a0, a1, a2, a3, c0, c1);
                    } else {
                        uint32_t b0, b1, b2, b3;
                        ldsm_x4(Bb + 24 * 208 + bRow4 + ks * 32, b0, b1, b2, b3);
                        mma16816(acc[0], a0, a1, a2, a3, b0, b1);
                        mma16816(acc[1], a0, a1, a2, a3, b2, b3);
                    }
                }
            }
        }
    }

    // denominator (global col 32 = ng==1, acc[1], t==0)
    if (w < 12 && ng == 1 && t == 0) {
        den_s[mp * 16 + g] = acc[1][0];
        den_s[mp * 16 + g + 8] = acc[1][2];
    }
    __syncthreads();

    if (w < 12) {
        int b = bh >> 3, h = bh & 7;
#pragma unroll
        for (int mi = 0; mi < 2; mi++) {
            int rr = mp * 16 + g + mi * 8;
            int q = q0 + rr;
            if (q < SSZ) {
                float dinv = 1.f / den_s[rr];
                float* orow = out + ((size_t)b * SSZ + q) * EE + h * 32;
                if (ng == 0) {
#pragma unroll
                    for (int nt = 0; nt < 3; nt++) {
                        int col = nt * 8 + 2 * t;
                        orow[col]     = acc[nt][mi * 2]     * dinv;
                        orow[col + 1] = acc[nt][mi * 2 + 1] * dinv;
                    }
                } else {
                    int col = 24 + 2 * t;
                    orow[col]     = acc[0][mi * 2]     * dinv;
                    orow[col + 1] = acc[0][mi * 2 + 1] * dinv;
                }
            }
        }
    }
}

// ---------------------------------------------------------------------------
extern "C" void kernel_launch(void* const* d_in, const int* in_sizes, int n_in,
                              void* d_out, int out_size)
{
    const float* x  = (const float*)d_in[0];
    const float* Wq = (const float*)d_in[1];
    const float* bq = (const float*)d_in[2];
    const float* Wk = (const float*)d_in[3];
    const float* bk = (const float*)d_in[4];
    const float* Wv = (const float*)d_in[5];
    const float* bv = (const float*)d_in[6];
    float* out = (float*)d_out;

    {
        dim3 grid(12, 128);
        proj_kernel<<<grid, 256>>>(x, Wq, bq, Wk, bk, Wv, bv);
    }
    {
        const int total = NBH * KKEY * 32;
        vsum_kernel<<<(total + 255) / 256, 256>>>();
    }
    {
        cudaFuncSetAttribute(attn_kernel,
                             cudaFuncAttributeMaxDynamicSharedMemorySize,
                             SMEM_TOTAL);
        dim3 grid(NQT, NBH);
        attn_kernel<<<grid, NTH, SMEM_TOTAL>>>(out);
    }
}

// round 10
// speedup vs baseline: 2.2359x; 1.1411x over previous
#include <cuda_runtime.h>
#include <cuda_bf16.h>
#include <cstdint>

#define NBH   32
#define SSZ   2048
#define EE    256
#define HH    8
#define KKEY  2016
#define WWIN  33
#define TQ    96
#define NKT   21
#define NQT   22
#define NTH   512
#define NCHUNK 381
#define SCALE 0.17677669529663687f

#define QLD   104     // bf16 stride for QA/KB/P/V tiles (208 bytes)
#define GLD   131     // fp32 word stride for G (odd -> conflict-free diag reads)

// attn smem byte offsets
#define OFF_TQQ  0
#define OFF_TKK  768
#define OFF_TLEN 1536
#define OFF_DEN  2304
#define OFF_QA   2688        // 128 x 208
#define OFF_KB0  29312       // 128 x 208
#define OFF_KB1  55936
#define OFF_G    82560       // 128 x 131 x 4 = 67072
#define OFF_PH   149632      // 96 x 208
#define OFF_PL   169600
#define OFF_VH0  189568      // 40 x 208
#define OFF_VL0  197888
#define OFF_VH1  206208
#define OFF_VL1  214528
#define SMEM_TOTAL 222848

// proj GEMM config: C[8192,768] = Axs[8192,768] @ WT[768,768]^T  (bf16 split)
#define PJ_K    768
#define PJ_NCH  12
#define PJ_LDA  144            // 64 bf16 + 8 pad bytes
#define PJ_TILE (128 * PJ_LDA) // 18432
#define PJ_A0   0
#define PJ_B0   18432
#define PJ_A1   36864
#define PJ_B1   55296
#define PJ_SMEM 73728

// device scratch (no runtime allocation allowed)
__device__ __align__(16) __nv_bfloat16 g_xs[(size_t)8192 * PJ_K];   // [hi|lo|hi]
__device__ __align__(16) __nv_bfloat16 g_wT[(size_t)768 * PJ_K];    // [hi|hi|lo] (n-major)
__device__ __align__(16) __nv_bfloat16 g_qA[(size_t)NBH * SSZ * 96];
__device__ __align__(16) __nv_bfloat16 g_kB[(size_t)NBH * SSZ * 96];
__device__ __align__(16) float         g_v [(size_t)NBH * SSZ * 32];
__device__ __align__(16) __nv_bfloat16 g_vsH[(size_t)NBH * 32 * KKEY];
__device__ __align__(16) __nv_bfloat16 g_vsL[(size_t)NBH * 32 * KKEY];

// ---------------- PTX helpers ----------------
__device__ __forceinline__ uint32_t smem_u32(const void* p) {
    uint32_t a;
    asm("{ .reg .u64 t; cvta.to.shared.u64 t, %1; cvt.u32.u64 %0, t; }"
        : "=r"(a) : "l"(p));
    return a;
}
__device__ __forceinline__ void mma16816(float* c, uint32_t a0, uint32_t a1,
                                         uint32_t a2, uint32_t a3,
                                         uint32_t b0, uint32_t b1)
{
    asm volatile(
        "mma.sync.aligned.m16n8k16.row.col.f32.bf16.bf16.f32 "
        "{%0,%1,%2,%3}, {%4,%5,%6,%7}, {%8,%9}, {%0,%1,%2,%3};"
        : "+f"(c[0]), "+f"(c[1]), "+f"(c[2]), "+f"(c[3])
        : "r"(a0), "r"(a1), "r"(a2), "r"(a3), "r"(b0), "r"(b1));
}
__device__ __forceinline__ void ldsm_x4(uint32_t addr, uint32_t& r0, uint32_t& r1,
                                        uint32_t& r2, uint32_t& r3)
{
    asm volatile("ldmatrix.sync.aligned.m8n8.x4.shared.b16 {%0,%1,%2,%3}, [%4];"
                 : "=r"(r0), "=r"(r1), "=r"(r2), "=r"(r3) : "r"(addr));
}
__device__ __forceinline__ void ldsm_x2(uint32_t addr, uint32_t& r0, uint32_t& r1)
{
    asm volatile("ldmatrix.sync.aligned.m8n8.x2.shared.b16 {%0,%1}, [%2];"
                 : "=r"(r0), "=r"(r1) : "r"(addr));
}
#define CP_ASYNC16(dst, src) \
    asm volatile("cp.async.cg.shared.global [%0], [%1], 16;" :: "r"(dst), "l"(src))
#define CP_COMMIT() asm volatile("cp.async.commit_group;" ::: "memory")
#define CP_WAIT0()  asm volatile("cp.async.wait_group 0;" ::: "memory")
#define CP_WAIT1()  asm volatile("cp.async.wait_group 1;" ::: "memory")

// ---------------------------------------------------------------------------
// Kernel 0a: split x -> packed bf16 [hi|lo|hi] rows of 768
// ---------------------------------------------------------------------------
__global__ void xsplit_kernel(const float* __restrict__ x)
{
    int idx = blockIdx.x * blockDim.x + threadIdx.x;
    if (idx >= 8192 * 256) return;
    int m = idx >> 8, k = idx & 255;
    float v = x[idx];
    __nv_bfloat16 hi = __float2bfloat16(v);
    __nv_bfloat16 lo = __float2bfloat16(v - __bfloat162float(hi));
    size_t rb = (size_t)m * PJ_K;
    g_xs[rb + k] = hi;
    g_xs[rb + 256 + k] = lo;
    g_xs[rb + 512 + k] = hi;
}

// ---------------------------------------------------------------------------
// Kernel 0b: split W^T -> packed bf16 [hi|hi|lo] rows of 768 (n-major)
// ---------------------------------------------------------------------------
__global__ void wsplit_kernel(const float* __restrict__ Wq,
                              const float* __restrict__ Wk,
                              const float* __restrict__ Wv)
{
    int idx = blockIdx.x * blockDim.x + threadIdx.x;
    if (idx >= 768 * 256) return;
    int n = idx >> 8, k = idx & 255;
    const float* Wsel = (n < 256) ? Wq : (n < 512) ? Wk : Wv;
    float v = Wsel[(size_t)k * 256 + (n & 255)];
    __nv_bfloat16 hi = __float2bfloat16(v);
    __nv_bfloat16 lo = __float2bfloat16(v - __bfloat162float(hi));
    size_t rb = (size_t)n * PJ_K;
    g_wT[rb + k] = hi;
    g_wT[rb + 256 + k] = hi;
    g_wT[rb + 512 + k] = lo;
}

// ---------------------------------------------------------------------------
// Kernel 1: HMMA projection.  C[8192,768] -> split-scatter epilogue.
// 128x128 out tiles, 8 warps (2m x 4n), K chunks of 64, double-buffered.
// ---------------------------------------------------------------------------
__device__ __forceinline__ void pj_load(uint32_t sb, uint32_t aoff, uint32_t boff,
                                        int m0, int n0, int ch, int tid)
{
    for (int i = tid; i < 1024; i += 256) {
        int r = i >> 3, cc = i & 7;
        const void* src = g_xs + (size_t)(m0 + r) * PJ_K + ch * 64 + cc * 8;
        CP_ASYNC16(sb + aoff + r * PJ_LDA + cc * 16, src);
    }
    for (int i = tid; i < 1024; i += 256) {
        int r = i >> 3, cc = i & 7;
        const void* src = g_wT + (size_t)(n0 + r) * PJ_K + ch * 64 + cc * 8;
        CP_ASYNC16(sb + boff + r * PJ_LDA + cc * 16, src);
    }
}

__global__ __launch_bounds__(256) void proj_mma_kernel(
    const float* __restrict__ bq, const float* __restrict__ bk,
    const float* __restrict__ bv)
{
    extern __shared__ char ps[];
    uint32_t sb = smem_u32(ps);
    int tid = threadIdx.x;
    int w = tid >> 5, lane = tid & 31;
    int g = lane >> 2, t = lane & 3;
    int m0 = blockIdx.y * 128, n0 = blockIdx.x * 128;
    int wm = w >> 2, wn = w & 3;

    float c[4][4][4];
#pragma unroll
    for (int i = 0; i < 4; i++)
#pragma unroll
        for (int j = 0; j < 4; j++)
#pragma unroll
            for (int k = 0; k < 4; k++) c[i][j][k] = 0.f;

    pj_load(sb, PJ_A0, PJ_B0, m0, n0, 0, tid);
    CP_COMMIT();

    for (int ch = 0; ch < PJ_NCH; ch++) {
        uint32_t ab = (ch & 1) ? PJ_A1 : PJ_A0;
        uint32_t bb = (ch & 1) ? PJ_B1 : PJ_B0;
        if (ch + 1 < PJ_NCH) {
            pj_load(sb, (ch & 1) ? PJ_A0 : PJ_A1, (ch & 1) ? PJ_B0 : PJ_B1,
                    m0, n0, ch + 1, tid);
            CP_COMMIT();
            CP_WAIT1();
        } else {
            CP_WAIT0();
        }
        __syncthreads();

        uint32_t aAddr = sb + ab + (uint32_t)(wm * 64 + (lane & 15)) * PJ_LDA
                       + (lane >> 4) * 16;
        uint32_t bAddr = sb + bb + (uint32_t)(wn * 32 + (lane & 15)) * PJ_LDA
                       + (lane >> 4) * 16;
#pragma unroll
        for (int k16 = 0; k16 < 4; k16++) {
            uint32_t b00, b01, b02, b03, b10, b11, b12, b13;
            ldsm_x4(bAddr + k16 * 32, b00, b01, b02, b03);
            ldsm_x4(bAddr + 16 * PJ_LDA + k16 * 32, b10, b11, b12, b13);
#pragma unroll
            for (int mt = 0; mt < 4; mt++) {
                uint32_t a0, a1, a2, a3;
                ldsm_x4(aAddr + (uint32_t)(mt * 16) * PJ_LDA + k16 * 32,
                        a0, a1, a2, a3);
                mma16816(c[mt][0], a0, a1, a2, a3, b00, b02);
                mma16816(c[mt][1], a0, a1, a2, a3, b01, b03);
                mma16816(c[mt][2], a0, a1, a2, a3, b10, b12);
                mma16816(c[mt][3], a0, a1, a2, a3, b11, b13);
            }
        }
        __syncthreads();
    }

    // epilogue: bias + split-scatter
    int msel = n0 >> 8;
    const float* bsel = (msel == 0) ? bq : (msel == 1) ? bk : bv;
#pragma unroll
    for (int mt = 0; mt < 4; mt++)
#pragma unroll
        for (int nt = 0; nt < 4; nt++)
#pragma unroll
            for (int j = 0; j < 4; j++) {
                int row = m0 + wm * 64 + mt * 16 + g + (j >> 1) * 8;
                int e = n0 + wn * 32 + nt * 8 + 2 * t + (j & 1);
                int ecol = e & 255;
                int h = ecol >> 5, d = ecol & 31;
                int b = row >> 11, s = row & 2047;
                float val = c[mt][nt][j] + bsel[ecol];
                if (msel == 2) {
                    g_v[(((size_t)(b * HH + h) * SSZ + s) * 32) + d] = val;
                } else {
                    __nv_bfloat16 hi = __float2bfloat16(val);
                    __nv_bfloat16 lo = __float2bfloat16(val - __bfloat162float(hi));
                    size_t rb = ((size_t)(b * HH + h) * SSZ + s) * 96;
                    if (msel == 0) {
                        g_qA[rb + d] = hi;
                        g_qA[rb + 32 + d] = lo;
                        g_qA[rb + 64 + d] = hi;
                    } else {
                        g_kB[rb + d] = hi;
                        g_kB[rb + 32 + d] = hi;
                        g_kB[rb + 64 + d] = lo;
                    }
                }
            }
}

// ---------------------------------------------------------------------------
// Kernel 2: transposed split sliding V-sums
// ---------------------------------------------------------------------------
__global__ void vsum_kernel()
{
    int idx = blockIdx.x * blockDim.x + threadIdx.x;
    const int total = NBH * KKEY * 32;
    if (idx >= total) return;
    int d = idx & 31;
    int k = (idx >> 5) % KKEY;
    int bh = idx / (32 * KKEY);
    const float* vp = &g_v[((size_t)bh * SSZ + k) * 32 + d];
    float s = 0.f;
#pragma unroll
    for (int w = 0; w < WWIN; w++) s += vp[w * 32];
    __nv_bfloat16 hi = __float2bfloat16(s);
    __nv_bfloat16 lo = __float2bfloat16(s - __bfloat162float(hi));
    size_t o = ((size_t)bh * 32 + d) * KKEY + k;
    g_vsH[o] = hi;
    g_vsL[o] = lo;
}

// ---------------------------------------------------------------------------
// G phase: 8 warps (4m x 2n of 32x64), two 32-col halves to cap registers
// ---------------------------------------------------------------------------
__device__ __forceinline__ void compute_G(char* sm, uint32_t sb, uint32_t kbuf_off,
                                          int w, int lane)
{
    float* G = (float*)(sm + OFF_G);
    int g = lane >> 2, t = lane & 3;
    int mw = w >> 1, nw = w & 1;
    int r0 = mw * 32, kb = nw * 64;
    uint32_t aG0 = sb + OFF_QA + (uint32_t)(r0 + (lane & 15)) * 208
                 + (lane >> 4) * 16;
    uint32_t aG1 = aG0 + 16 * 208;
    uint32_t bRow4 = ((uint32_t)(lane >> 4) * 8 + (lane & 7)) * 208
                   + ((lane >> 3) & 1) * 16;
    uint32_t kbase = sb + kbuf_off;

#pragma unroll
    for (int half = 0; half < 2; half++) {
        float c[2][4][4];
#pragma unroll
        for (int mi = 0; mi < 2; mi++)
#pragma unroll
            for (int ni = 0; ni < 4; ni++)
#pragma unroll
                for (int j = 0; j < 4; j++) c[mi][ni][j] = 0.f;
#pragma unroll
        for (int ks = 0; ks < 6; ks++) {
            uint32_t a0, a1, a2, a3, a4, a5, a6, a7;
            ldsm_x4(aG0 + ks * 32, a0, a1, a2, a3);
            ldsm_x4(aG1 + ks * 32, a4, a5, a6, a7);
#pragma unroll
            for (int p2 = 0; p2 < 2; p2++) {
                int colb = kb + half * 32 + p2 * 16;
                uint32_t b0, b1, b2, b3;
                ldsm_x4(kbase + (uint32_t)colb * 208 + bRow4 + ks * 32,
                        b0, b1, b2, b3);
                mma16816(c[0][2 * p2],     a0, a1, a2, a3, b0, b1);
                mma16816(c[1][2 * p2],     a4, a5, a6, a7, b0, b1);
                mma16816(c[0][2 * p2 + 1], a0, a1, a2, a3, b2, b3);
                mma16816(c[1][2 * p2 + 1], a4, a5, a6, a7, b2, b3);
            }
        }
#pragma unroll
        for (int mi = 0; mi < 2; mi++)
#pragma unroll
            for (int ni = 0; ni < 4; ni++) {
                int r = r0 + mi * 16 + g;
                int col = kb + half * 32 + ni * 8 + 2 * t;
                G[r * GLD + col]           = c[mi][ni][0];
                G[r * GLD + col + 1]       = c[mi][ni][1];
                G[(r + 8) * GLD + col]     = c[mi][ni][2];
                G[(r + 8) * GLD + col + 1] = c[mi][ni][3];
            }
    }
}

// ---------------------------------------------------------------------------
// Kernel 3: HMMA attention with G/PV overlap (warp specialization)
// ---------------------------------------------------------------------------
__global__ __launch_bounds__(NTH, 1) void attn_kernel(float* __restrict__ out)
{
    extern __shared__ char sm[];
    uint32_t sb = smem_u32(sm);
    uint16_t* tqq  = (uint16_t*)(sm + OFF_TQQ);
    uint16_t* tkk  = (uint16_t*)(sm + OFF_TKK);
    uint16_t* tlen = (uint16_t*)(sm + OFF_TLEN);
    float* den_s = (float*)(sm + OFF_DEN);
    float* G = (float*)(sm + OFF_G);
    __nv_bfloat16* PH = (__nv_bfloat16*)(sm + OFF_PH);
    __nv_bfloat16* PL = (__nv_bfloat16*)(sm + OFF_PL);

    int tid = threadIdx.x;
    int w = tid >> 5, lane = tid & 31;
    int g = lane >> 2, t = lane & 3;
    int qt = blockIdx.x, bh = blockIdx.y;
    int q0 = qt * TQ;

    if (tid == 0) {
        // chunk table, t0-major: warp lanes on adjacent diagonals (conflict-free)
        int c = 0;
        for (int t0 = 0; t0 < TQ; t0 += 32) {
            for (int d = -95; d <= 95; d++) {
                int ad = d < 0 ? -d : d;
                int L = 96 - ad;
                if (t0 >= L) continue;
                int qs0 = d > 0 ? d : 0, ks0 = d > 0 ? 0 : -d;
                tqq[c] = (uint16_t)(qs0 + t0);
                tkk[c] = (uint16_t)(ks0 + t0);
                int l = L - t0; tlen[c] = (uint16_t)(l < 32 ? l : 32);
                c++;
            }
        }
    }

    // Q halo tile (rows q0-16 .. q0+111), zero-padded
    {
        const uint4* qsrc = (const uint4*)(g_qA + (size_t)bh * SSZ * 96);
        for (int idx = tid; idx < 128 * 12; idx += NTH) {
            int r = idx / 12, cb = idx % 12;
            int gq = q0 - 16 + r;
            uint4 v = make_uint4(0, 0, 0, 0);
            if (gq >= 0 && gq < SSZ) v = qsrc[(size_t)gq * 12 + cb];
            *(uint4*)(sm + OFF_QA + r * 208 + cb * 16) = v;
        }
    }
    // const V rows 32..39 for BOTH buffers; VH row32 = ones (denominator)
    for (int idx = tid; idx < 416; idx += NTH) {
        int buf = idx / 208, rem = idx % 208;
        int tt = rem / 104, r2 = rem % 104;
        int r = 32 + r2 / 13, cb = r2 % 13;
        uint4 v = make_uint4(0, 0, 0, 0);
        if (tt == 0 && r == 32)
            v = make_uint4(0x3F803F80u, 0x3F803F80u, 0x3F803F80u, 0x3F803F80u);
        int off = tt ? (buf ? OFF_VL1 : OFF_VL0) : (buf ? OFF_VH1 : OFF_VH0);
        *(uint4*)(sm + off + r * 208 + cb * 16) = v;
    }

    const uint4* ksrc = (const uint4*)(g_kB + (size_t)bh * SSZ * 96);

    // prologue: KB(0)->kb0, V(0)->v0, KB(1)->kb1
    {
        for (int idx = tid; idx < 1536; idx += NTH) {
            int r = idx / 12, cb = idx % 12;
            CP_ASYNC16(sb + OFF_KB0 + r * 208 + cb * 16,
                       (const void*)(ksrc + (size_t)r * 12 + cb));
            CP_ASYNC16(sb + OFF_KB1 + r * 208 + cb * 16,
                       (const void*)(ksrc + (size_t)(TQ + r) * 12 + cb));
        }
        for (int idx = tid; idx < 768; idx += NTH) {
            int tt = idx / 384, rem = idx % 384;
            int d = rem / 12, cb = rem % 12;
            const __nv_bfloat16* src = (tt ? g_vsL : g_vsH)
                + ((size_t)bh * 32 + d) * KKEY + cb * 8;
            CP_ASYNC16(sb + (tt ? OFF_VL0 : OFF_VH0) + d * 208 + cb * 16,
                       (const void*)src);
        }
        CP_COMMIT();
        CP_WAIT0();
    }
    __syncthreads();

    // G(0)
    if (w < 8) compute_G(sm, sb, OFF_KB0, w, lane);

    // PV addressing (warps 8..13 fixed stripe; 14/15 iterate)
    uint32_t bRow4 = ((uint32_t)(lane >> 4) * 8 + (lane & 7)) * 208
                   + ((lane >> 3) & 1) * 16;
    uint32_t bRow2 = (uint32_t)(lane & 7) * 208 + ((lane >> 3) & 1) * 16;
    uint32_t aPHf = sb + OFF_PH + (uint32_t)((w - 8) * 16 + (lane & 15)) * 208
                  + (lane >> 4) * 16;
    uint32_t aPLf = aPHf + (OFF_PL - OFF_PH);

    float acc[4][4];
#pragma unroll
    for (int i = 0; i < 4; i++)
#pragma unroll
        for (int j = 0; j < 4; j++) acc[i][j] = 0.f;

    for (int kt = 0; kt < NKT; kt++) {
        __syncthreads();   // (A) G(kt) visible; PV(kt-1) done with P/V

        // --- phase C(kt): scores -> P; warps 12-15 issue prefetch ---
        if (tid < NCHUNK) {
            int qq = tqq[tid], kk = tkk[tid], len = tlen[tid];
            float s = 0.f;
#pragma unroll
            for (int ww = 0; ww < WWIN; ww++)
                s += G[(qq + ww) * GLD + kk + ww];
            {
                float p = __expf(s * SCALE);
                __nv_bfloat16 hi = __float2bfloat16(p);
                __nv_bfloat16 lo = __float2bfloat16(p - __bfloat162float(hi));
                int off = qq * QLD + kk;
                PH[off] = hi;
                PL[off] = lo;
            }
#pragma unroll 4
            for (int u = 1; u < 32; u++) {
                int uu = (u < len) ? u : (len - 1);
                s += G[(qq + uu + 32) * GLD + (kk + uu + 32)]
                   - G[(qq + uu - 1) * GLD + (kk + uu - 1)];
                if (u < len) {
                    float p = __expf(s * SCALE);
                    __nv_bfloat16 hi = __float2bfloat16(p);
                    __nv_bfloat16 lo = __float2bfloat16(p - __bfloat162float(hi));
                    int off = (qq + u) * QLD + (kk + u);
                    PH[off] = hi;
                    PL[off] = lo;
                }
            }
        } else if (tid >= 384) {
            int pt = tid - 384;          // 128 helper threads
            if (kt + 2 < NKT) {          // KB(kt+2) -> kbuf[kt&1]
                int k0n = (kt + 2) * TQ;
                uint32_t kdst = sb + ((kt & 1) ? OFF_KB1 : OFF_KB0);
                for (int idx = pt; idx < 1536; idx += 128) {
                    int r = idx / 12, cb = idx % 12;
                    CP_ASYNC16(kdst + r * 208 + cb * 16,
                               (const void*)(ksrc + (size_t)(k0n + r) * 12 + cb));
                }
            }
            if (kt + 1 < NKT) {          // V(kt+1) -> vbuf[(kt+1)&1]
                int k0n = (kt + 1) * TQ;
                for (int idx = pt; idx < 768; idx += 128) {
                    int tt = idx / 384, rem = idx % 384;
                    int d = rem / 12, cb = rem % 12;
                    const __nv_bfloat16* src = (tt ? g_vsL : g_vsH)
                        + ((size_t)bh * 32 + d) * KKEY + k0n + cb * 8;
                    int off = tt ? (((kt + 1) & 1) ? OFF_VL1 : OFF_VL0)
                                 : (((kt + 1) & 1) ? OFF_VH1 : OFF_VH0);
                    CP_ASYNC16(sb + off + d * 208 + cb * 16, (const void*)src);
                }
            }
        }
        CP_COMMIT();
        CP_WAIT1();
        __syncthreads();   // (B) P visible; KB(kt+1)/V(kt) arrived

        // --- overlap: G(kt+1) on warps 0-7, PV(kt) on warps 8-15 ---
        if (w < 8) {
            if (kt + 1 < NKT)
                compute_G(sm, sb, ((kt + 1) & 1) ? OFF_KB1 : OFF_KB0, w, lane);
        } else {
            uint32_t vhb = sb + ((kt & 1) ? OFF_VH1 : OFF_VH0);
            uint32_t vlb = sb + ((kt & 1) ? OFF_VL1 : OFF_VL0);
            if (w < 14) {
#pragma unroll
                for (int pass = 0; pass < 3; pass++) {
                    uint32_t Ab = (pass == 1) ? aPLf : aPHf;
                    uint32_t Bb = (pass == 2) ? vlb : vhb;
#pragma unroll
                    for (int ks = 0; ks < 6; ks++) {
                        uint32_t a0, a1, a2, a3;
                        ldsm_x4(Ab + ks * 32, a0, a1, a2, a3);
                        uint32_t b0, b1, b2, b3;
                        ldsm_x4(Bb + bRow4 + ks * 32, b0, b1, b2, b3);
                        mma16816(acc[0], a0, a1, a2, a3, b0, b1);
                        mma16816(acc[1], a0, a1, a2, a3, b2, b3);
                        ldsm_x4(Bb + 16 * 208 + bRow4 + ks * 32, b0, b1, b2, b3);
                        mma16816(acc[2], a0, a1, a2, a3, b0, b1);
                        mma16816(acc[3], a0, a1, a2, a3, b2, b3);
                    }
                }
            } else {
                int base = (w - 14) * 3;
#pragma unroll
                for (int st = 0; st < 3; st++) {
                    uint32_t aPh = sb + OFF_PH
                        + (uint32_t)((base + st) * 16 + (lane & 15)) * 208
                        + (lane >> 4) * 16;
                    uint32_t aPl = aPh + (OFF_PL - OFF_PH);
#pragma unroll
                    for (int pass = 0; pass < 3; pass++) {
                        uint32_t Ab = (pass == 1) ? aPl : aPh;
                        uint32_t Bb = (pass == 2) ? vlb : vhb;
#pragma unroll
                        for (int ks = 0; ks < 6; ks++) {
                            uint32_t a0, a1, a2, a3;
                            ldsm_x4(Ab + ks * 32, a0, a1, a2, a3);
                            uint32_t b0, b1;
                            ldsm_x2(Bb + 32 * 208 + bRow2 + ks * 32, b0, b1);
                            mma16816(acc[st], a0, a1, a2, a3, b0, b1);
                        }
                    }
                }
            }
        }
    }

    // denominator from warps 14/15 (col 32 -> t==0, j 0/2)
    if (w >= 14 && t == 0) {
        int base = (w - 14) * 3;
#pragma unroll
        for (int st = 0; st < 3; st++) {
            den_s[(base + st) * 16 + g]     = acc[st][0];
            den_s[(base + st) * 16 + g + 8] = acc[st][2];
        }
    }
    __syncthreads();

    if (w >= 8 && w < 14) {
        int stripe = w - 8;
        int b = bh >> 3, h = bh & 7;
#pragma unroll
        for (int mi = 0; mi < 2; mi++) {
            int rr = stripe * 16 + g + mi * 8;
            int q = q0 + rr;
            if (q < SSZ) {
                float dinv = 1.f / den_s[rr];
                float* orow = out + ((size_t)b * SSZ + q) * EE + h * 32;
#pragma unroll
                for (int nt = 0; nt < 4; nt++) {
                    int col = nt * 8 + 2 * t;
                    orow[col]     = acc[nt][mi * 2]     * dinv;
                    orow[col + 1] = acc[nt][mi * 2 + 1] * dinv;
                }
            }
        }
    }
}

// ---------------------------------------------------------------------------
extern "C" void kernel_launch(void* const* d_in, const int* in_sizes, int n_in,
                              void* d_out, int out_size)
{
    const float* x  = (const float*)d_in[0];
    const float* Wq = (const float*)d_in[1];
    const float* bq = (const float*)d_in[2];
    const float* Wk = (const float*)d_in[3];
    const float* bk = (const float*)d_in[4];
    const float* Wv = (const float*)d_in[5];
    const float* bv = (const float*)d_in[6];
    float* out = (float*)d_out;

    xsplit_kernel<<<(8192 * 256 + 255) / 256, 256>>>(x);
    wsplit_kernel<<<(768 * 256 + 255) / 256, 256>>>(Wq, Wk, Wv);
    {
        cudaFuncSetAttribute(proj_mma_kernel,
                             cudaFuncAttributeMaxDynamicSharedMemorySize,
                             PJ_SMEM);
        dim3 grid(6, 64);
        proj_mma_kernel<<<grid, 256, PJ_SMEM>>>(bq, bk, bv);
    }
    {
        const int total = NBH * KKEY * 32;
        vsum_kernel<<<(total + 255) / 256, 256>>>();
    }
    {
        cudaFuncSetAttribute(attn_kernel,
                             cudaFuncAttributeMaxDynamicSharedMemorySize,
                             SMEM_TOTAL);
        dim3 grid(NQT, NBH);
        attn_kernel<<<grid, NTH, SMEM_TOTAL>>>(out);
    }
}

// round 13
// speedup vs baseline: 2.4756x; 1.1072x over previous
#include <cuda_runtime.h>
#include <cuda_bf16.h>
#include <cstdint>

#define NBH   32
#define SSZ   2048
#define EE    256
#define HH    8
#define KKEY  2016
#define WWIN  33
#define TQ    96
#define NKT   21
#define NQT   22
#define NTILES (NQT * NBH)
#define NTH   512
#define NCHUNK 381
#define SCALE 0.17677669529663687f

#define QLD   104     // bf16 stride for QA/KB/P/V tiles (208 bytes)
#define GLD   131     // fp32 word stride for G (odd -> conflict-free diag reads)

// attn smem byte offsets
#define OFF_TQQ  0
#define OFF_TKK  768
#define OFF_TLEN 1536        // ends 2298
#define OFF_NEXT 2300        // next-tile broadcast slot (4B, in the gap)
#define OFF_DEN  2304        // 96 floats -> ends 2688
#define OFF_QA   2688        // 128 x 208
#define OFF_KB0  29312       // 128 x 208
#define OFF_KB1  55936
#define OFF_G    82560       // 128 x 131 x 4 = 67072
#define OFF_PH   149632      // 96 x 208
#define OFF_PL   169600
#define OFF_VH0  189568      // 40 x 208
#define OFF_VL0  197888
#define OFF_VH1  206208
#define OFF_VL1  214528
#define SMEM_TOTAL 222848

// proj GEMM config
#define PJ_K    768
#define PJ_NCH  12
#define PJ_LDA  144
#define PJ_A0   0
#define PJ_B0   18432
#define PJ_A1   36864
#define PJ_B1   55296
#define PJ_SMEM 73728

// device scratch (no runtime allocation allowed)
__device__ __align__(16) __nv_bfloat16 g_xs[(size_t)8192 * PJ_K];   // [hi|lo|hi]
__device__ __align__(16) __nv_bfloat16 g_wT[(size_t)768 * PJ_K];    // [hi|hi|lo]
__device__ __align__(16) __nv_bfloat16 g_qA[(size_t)NBH * SSZ * 96];
__device__ __align__(16) __nv_bfloat16 g_kB[(size_t)NBH * SSZ * 96];
__device__ __align__(16) float         g_v [(size_t)NBH * SSZ * 32];
__device__ __align__(16) __nv_bfloat16 g_vsH[(size_t)NBH * 32 * KKEY];
__device__ __align__(16) __nv_bfloat16 g_vsL[(size_t)NBH * 32 * KKEY];
__device__ int g_ctr;

// ---------------- PTX helpers ----------------
__device__ __forceinline__ uint32_t smem_u32(const void* p) {
    uint32_t a;
    asm("{ .reg .u64 t; cvta.to.shared.u64 t, %1; cvt.u32.u64 %0, t; }"
        : "=r"(a) : "l"(p));
    return a;
}
__device__ __forceinline__ void mma16816(float* c, uint32_t a0, uint32_t a1,
                                         uint32_t a2, uint32_t a3,
                                         uint32_t b0, uint32_t b1)
{
    asm volatile(
        "mma.sync.aligned.m16n8k16.row.col.f32.bf16.bf16.f32 "
        "{%0,%1,%2,%3}, {%4,%5,%6,%7}, {%8,%9}, {%0,%1,%2,%3};"
        : "+f"(c[0]), "+f"(c[1]), "+f"(c[2]), "+f"(c[3])
        : "r"(a0), "r"(a1), "r"(a2), "r"(a3), "r"(b0), "r"(b1));
}
__device__ __forceinline__ void ldsm_x4(uint32_t addr, uint32_t& r0, uint32_t& r1,
                                        uint32_t& r2, uint32_t& r3)
{
    asm volatile("ldmatrix.sync.aligned.m8n8.x4.shared.b16 {%0,%1,%2,%3}, [%4];"
                 : "=r"(r0), "=r"(r1), "=r"(r2), "=r"(r3) : "r"(addr));
}
__device__ __forceinline__ void ldsm_x2(uint32_t addr, uint32_t& r0, uint32_t& r1)
{
    asm volatile("ldmatrix.sync.aligned.m8n8.x2.shared.b16 {%0,%1}, [%2];"
                 : "=r"(r0), "=r"(r1) : "r"(addr));
}
#define CP_ASYNC16(dst, src) \
    asm volatile("cp.async.cg.shared.global [%0], [%1], 16;" :: "r"(dst), "l"(src))
#define CP_COMMIT() asm volatile("cp.async.commit_group;" ::: "memory")
#define CP_WAIT0()  asm volatile("cp.async.wait_group 0;" ::: "memory")
#define CP_WAIT1()  asm volatile("cp.async.wait_group 1;" ::: "memory")

// ---------------------------------------------------------------------------
// Kernel 0a: split x -> packed bf16 [hi|lo|hi] rows of 768 (vectorized)
// ---------------------------------------------------------------------------
__global__ void xsplit_kernel(const float* __restrict__ x)
{
    int idx = blockIdx.x * blockDim.x + threadIdx.x;
    if (idx >= 8192 * 64) return;
    int m = idx >> 6, kq = (idx & 63) * 4;
    float4 v = *(const float4*)&x[(size_t)m * 256 + kq];
    float vv[4] = {v.x, v.y, v.z, v.w};
    __nv_bfloat16 h[4], l[4];
#pragma unroll
    for (int i = 0; i < 4; i++) {
        h[i] = __float2bfloat16(vv[i]);
        l[i] = __float2bfloat16(vv[i] - __bfloat162float(h[i]));
    }
    size_t rb = (size_t)m * PJ_K;
    *(uint2*)&g_xs[rb + kq]       = *(uint2*)h;
    *(uint2*)&g_xs[rb + 256 + kq] = *(uint2*)l;
    *(uint2*)&g_xs[rb + 512 + kq] = *(uint2*)h;
}

// ---------------------------------------------------------------------------
// Kernel 0b: split W^T -> packed bf16 [hi|hi|lo] (coalesced reads)
// ---------------------------------------------------------------------------
__global__ void wsplit_kernel(const float* __restrict__ Wq,
                              const float* __restrict__ Wk,
                              const float* __restrict__ Wv)
{
    int idx = blockIdx.x * blockDim.x + threadIdx.x;
    if (idx >= 768 * 256) return;
    int n = idx % 768, k = idx / 768;
    const float* Wsel = (n < 256) ? Wq : (n < 512) ? Wk : Wv;
    float v = Wsel[(size_t)k * 256 + (n & 255)];
    __nv_bfloat16 hi = __float2bfloat16(v);
    __nv_bfloat16 lo = __float2bfloat16(v - __bfloat162float(hi));
    size_t rb = (size_t)n * PJ_K;
    g_wT[rb + k] = hi;
    g_wT[rb + 256 + k] = hi;
    g_wT[rb + 512 + k] = lo;
}

// ---------------------------------------------------------------------------
// Kernel 1: HMMA projection
// ---------------------------------------------------------------------------
__device__ __forceinline__ void pj_load(uint32_t sb, uint32_t aoff, uint32_t boff,
                                        int m0, int n0, int ch, int tid)
{
    for (int i = tid; i < 1024; i += 256) {
        int r = i >> 3, cc = i & 7;
        const void* src = g_xs + (size_t)(m0 + r) * PJ_K + ch * 64 + cc * 8;
        CP_ASYNC16(sb + aoff + r * PJ_LDA + cc * 16, src);
    }
    for (int i = tid; i < 1024; i += 256) {
        int r = i >> 3, cc = i & 7;
        const void* src = g_wT + (size_t)(n0 + r) * PJ_K + ch * 64 + cc * 8;
        CP_ASYNC16(sb + boff + r * PJ_LDA + cc * 16, src);
    }
}

__global__ __launch_bounds__(256) void proj_mma_kernel(
    const float* __restrict__ bq, const float* __restrict__ bk,
    const float* __restrict__ bv)
{
    extern __shared__ char ps[];
    uint32_t sb = smem_u32(ps);
    int tid = threadIdx.x;
    int w = tid >> 5, lane = tid & 31;
    int g = lane >> 2, t = lane & 3;
    int m0 = blockIdx.y * 128, n0 = blockIdx.x * 128;
    int wm = w >> 2, wn = w & 3;

    float c[4][4][4];
#pragma unroll
    for (int i = 0; i < 4; i++)
#pragma unroll
        for (int j = 0; j < 4; j++)
#pragma unroll
            for (int k = 0; k < 4; k++) c[i][j][k] = 0.f;

    pj_load(sb, PJ_A0, PJ_B0, m0, n0, 0, tid);
    CP_COMMIT();

    for (int ch = 0; ch < PJ_NCH; ch++) {
        uint32_t ab = (ch & 1) ? PJ_A1 : PJ_A0;
        uint32_t bb = (ch & 1) ? PJ_B1 : PJ_B0;
        if (ch + 1 < PJ_NCH) {
            pj_load(sb, (ch & 1) ? PJ_A0 : PJ_A1, (ch & 1) ? PJ_B0 : PJ_B1,
                    m0, n0, ch + 1, tid);
            CP_COMMIT();
            CP_WAIT1();
        } else {
            CP_WAIT0();
        }
        __syncthreads();

        uint32_t aAddr = sb + ab + (uint32_t)(wm * 64 + (lane & 15)) * PJ_LDA
                       + (lane >> 4) * 16;
        uint32_t bAddr = sb + bb + (uint32_t)(wn * 32 + (lane & 15)) * PJ_LDA
                       + (lane >> 4) * 16;
#pragma unroll
        for (int k16 = 0; k16 < 4; k16++) {
            uint32_t b00, b01, b02, b03, b10, b11, b12, b13;
            ldsm_x4(bAddr + k16 * 32, b00, b01, b02, b03);
            ldsm_x4(bAddr + 16 * PJ_LDA + k16 * 32, b10, b11, b12, b13);
#pragma unroll
            for (int mt = 0; mt < 4; mt++) {
                uint32_t a0, a1, a2, a3;
                ldsm_x4(aAddr + (uint32_t)(mt * 16) * PJ_LDA + k16 * 32,
                        a0, a1, a2, a3);
                mma16816(c[mt][0], a0, a1, a2, a3, b00, b02);
                mma16816(c[mt][1], a0, a1, a2, a3, b01, b03);
                mma16816(c[mt][2], a0, a1, a2, a3, b10, b12);
                mma16816(c[mt][3], a0, a1, a2, a3, b11, b13);
            }
        }
        __syncthreads();
    }

    int msel = n0 >> 8;
    const float* bsel = (msel == 0) ? bq : (msel == 1) ? bk : bv;
#pragma unroll
    for (int mt = 0; mt < 4; mt++)
#pragma unroll
        for (int nt = 0; nt < 4; nt++)
#pragma unroll
            for (int j = 0; j < 4; j++) {
                int row = m0 + wm * 64 + mt * 16 + g + (j >> 1) * 8;
                int e = n0 + wn * 32 + nt * 8 + 2 * t + (j & 1);
                int ecol = e & 255;
                int h = ecol >> 5, d = ecol & 31;
                int b = row >> 11, s = row & 2047;
                float val = c[mt][nt][j] + bsel[ecol];
                if (msel == 2) {
                    g_v[(((size_t)(b * HH + h) * SSZ + s) * 32) + d] = val;
                } else {
                    __nv_bfloat16 hi = __float2bfloat16(val);
                    __nv_bfloat16 lo = __float2bfloat16(val - __bfloat162float(hi));
                    size_t rb = ((size_t)(b * HH + h) * SSZ + s) * 96;
                    if (msel == 0) {
                        g_qA[rb + d] = hi;
                        g_qA[rb + 32 + d] = lo;
                        g_qA[rb + 64 + d] = hi;
                    } else {
                        g_kB[rb + d] = hi;
                        g_kB[rb + 32 + d] = hi;
                        g_kB[rb + 64 + d] = lo;
                    }
                }
            }
}

// ---------------------------------------------------------------------------
// Kernel 2: sliding-window V sums, 8 outputs per thread (running sum)
// ---------------------------------------------------------------------------
__global__ void vsum_kernel()
{
    int idx = blockIdx.x * blockDim.x + threadIdx.x;
    const int KB8 = KKEY / 8;                  // 252
    const int total = NBH * 32 * KB8;
    if (idx >= total) return;
    int d  = idx & 31;
    int kb = (idx >> 5) % KB8;
    int bh = idx / (32 * KB8);
    int k0 = kb * 8;
    const float* vp = &g_v[((size_t)bh * SSZ + k0) * 32 + d];
    float s = 0.f;
#pragma unroll
    for (int w = 0; w < WWIN; w++) s += vp[w * 32];
    __nv_bfloat16 h8[8], l8[8];
#pragma unroll
    for (int i = 0; i < 8; i++) {
        __nv_bfloat16 hi = __float2bfloat16(s);
        h8[i] = hi;
        l8[i] = __float2bfloat16(s - __bfloat162float(hi));
        if (i < 7) s += vp[(WWIN + i) * 32] - vp[i * 32];
    }
    size_t o = ((size_t)bh * 32 + d) * KKEY + k0;
    *(uint4*)&g_vsH[o] = *(uint4*)h8;
    *(uint4*)&g_vsL[o] = *(uint4*)l8;
}

// ---------------------------------------------------------------------------
// work-queue counter init
// ---------------------------------------------------------------------------
__global__ void ctr_init_kernel() { g_ctr = 148; }

// ---------------------------------------------------------------------------
// G phase: 8 warps (4m x 2n of 32x64), two 32-col halves
// ---------------------------------------------------------------------------
__device__ __forceinline__ void compute_G(char* sm, uint32_t sb, uint32_t kbuf_off,
                                          int w, int lane)
{
    float* G = (float*)(sm + OFF_G);
    int g = lane >> 2, t = lane & 3;
    int mw = w >> 1, nw = w & 1;
    int r0 = mw * 32, kb = nw * 64;
    uint32_t aG0 = sb + OFF_QA + (uint32_t)(r0 + (lane & 15)) * 208
                 + (lane >> 4) * 16;
    uint32_t aG1 = aG0 + 16 * 208;
    uint32_t bRow4 = ((uint32_t)(lane >> 4) * 8 + (lane & 7)) * 208
                   + ((lane >> 3) & 1) * 16;
    uint32_t kbase = sb + kbuf_off;

#pragma unroll
    for (int half = 0; half < 2; half++) {
        float c[2][4][4];
#pragma unroll
        for (int mi = 0; mi < 2; mi++)
#pragma unroll
            for (int ni = 0; ni < 4; ni++)
#pragma unroll
                for (int j = 0; j < 4; j++) c[mi][ni][j] = 0.f;
#pragma unroll
        for (int ks = 0; ks < 6; ks++) {
            uint32_t a0, a1, a2, a3, a4, a5, a6, a7;
            ldsm_x4(aG0 + ks * 32, a0, a1, a2, a3);
            ldsm_x4(aG1 + ks * 32, a4, a5, a6, a7);
#pragma unroll
            for (int p2 = 0; p2 < 2; p2++) {
                int colb = kb + half * 32 + p2 * 16;
                uint32_t b0, b1, b2, b3;
                ldsm_x4(kbase + (uint32_t)colb * 208 + bRow4 + ks * 32,
                        b0, b1, b2, b3);
                mma16816(c[0][2 * p2],     a0, a1, a2, a3, b0, b1);
                mma16816(c[1][2 * p2],     a4, a5, a6, a7, b0, b1);
                mma16816(c[0][2 * p2 + 1], a0, a1, a2, a3, b2, b3);
                mma16816(c[1][2 * p2 + 1], a4, a5, a6, a7, b2, b3);
            }
        }
#pragma unroll
        for (int mi = 0; mi < 2; mi++)
#pragma unroll
            for (int ni = 0; ni < 4; ni++) {
                int r = r0 + mi * 16 + g;
                int col = kb + half * 32 + ni * 8 + 2 * t;
                G[r * GLD + col]           = c[mi][ni][0];
                G[r * GLD + col + 1]       = c[mi][ni][1];
                G[(r + 8) * GLD + col]     = c[mi][ni][2];
                G[(r + 8) * GLD + col + 1] = c[mi][ni][3];
            }
    }
}

// ---------------------------------------------------------------------------
// Kernel 3: persistent HMMA attention with G/PV overlap + work stealing
// ---------------------------------------------------------------------------
__global__ __launch_bounds__(NTH, 1) void attn_kernel(float* __restrict__ out)
{
    extern __shared__ char sm[];
    uint32_t sb = smem_u32(sm);
    uint16_t* tqq  = (uint16_t*)(sm + OFF_TQQ);
    uint16_t* tkk  = (uint16_t*)(sm + OFF_TKK);
    uint16_t* tlen = (uint16_t*)(sm + OFF_TLEN);
    float* den_s = (float*)(sm + OFF_DEN);
    int* next_s = (int*)(sm + OFF_NEXT);
    float* G = (float*)(sm + OFF_G);
    __nv_bfloat16* PH = (__nv_bfloat16*)(sm + OFF_PH);
    __nv_bfloat16* PL = (__nv_bfloat16*)(sm + OFF_PL);

    int tid = threadIdx.x;
    int w = tid >> 5, lane = tid & 31;
    int g = lane >> 2, t = lane & 3;

    if (tid == 0) {
        int c = 0;
        for (int t0 = 0; t0 < TQ; t0 += 32) {
            for (int d = -95; d <= 95; d++) {
                int ad = d < 0 ? -d : d;
                int L = 96 - ad;
                if (t0 >= L) continue;
                int qs0 = d > 0 ? d : 0, ks0 = d > 0 ? 0 : -d;
                tqq[c] = (uint16_t)(qs0 + t0);
                tkk[c] = (uint16_t)(ks0 + t0);
                int l = L - t0; tlen[c] = (uint16_t)(l < 32 ? l : 32);
                c++;
            }
        }
    }
    // const V rows 32..39 for BOTH buffers; VH row32 = ones (denominator)
    for (int idx = tid; idx < 416; idx += NTH) {
        int buf = idx / 208, rem = idx % 208;
        int tt = rem / 104, r2 = rem % 104;
        int r = 32 + r2 / 13, cb = r2 % 13;
        uint4 v = make_uint4(0, 0, 0, 0);
        if (tt == 0 && r == 32)
            v = make_uint4(0x3F803F80u, 0x3F803F80u, 0x3F803F80u, 0x3F803F80u);
        int off = tt ? (buf ? OFF_VL1 : OFF_VL0) : (buf ? OFF_VH1 : OFF_VH0);
        *(uint4*)(sm + off + r * 208 + cb * 16) = v;
    }

    // PV addressing constants
    uint32_t bRow4 = ((uint32_t)(lane >> 4) * 8 + (lane & 7)) * 208
                   + ((lane >> 3) & 1) * 16;
    uint32_t bRow2 = (uint32_t)(lane & 7) * 208 + ((lane >> 3) & 1) * 16;
    uint32_t aPHf = sb + OFF_PH + (uint32_t)((w - 8) * 16 + (lane & 15)) * 208
                  + (lane >> 4) * 16;
    uint32_t aPLf = aPHf + (OFF_PL - OFF_PH);

    float acc[4][4];
    int tile = blockIdx.x;

    for (;;) {
        int qt = tile % NQT, bh = tile / NQT;
        int q0 = qt * TQ;
        const uint4* qsrc = (const uint4*)(g_qA + (size_t)bh * SSZ * 96);
        const uint4* ksrc = (const uint4*)(g_kB + (size_t)bh * SSZ * 96);

        // per-tile prologue: Q halo, KB(0)->kb0, KB(1)->kb1, V(0)->v0
        for (int idx = tid; idx < 128 * 12; idx += NTH) {
            int r = idx / 12, cb = idx % 12;
            int gq = q0 - 16 + r;
            if (gq >= 0 && gq < SSZ)
                CP_ASYNC16(sb + OFF_QA + r * 208 + cb * 16,
                           (const void*)(qsrc + (size_t)gq * 12 + cb));
            else
                *(uint4*)(sm + OFF_QA + r * 208 + cb * 16) = make_uint4(0, 0, 0, 0);
        }
        for (int idx = tid; idx < 1536; idx += NTH) {
            int r = idx / 12, cb = idx % 12;
            CP_ASYNC16(sb + OFF_KB0 + r * 208 + cb * 16,
                       (const void*)(ksrc + (size_t)r * 12 + cb));
            CP_ASYNC16(sb + OFF_KB1 + r * 208 + cb * 16,
                       (const void*)(ksrc + (size_t)(TQ + r) * 12 + cb));
        }
        for (int idx = tid; idx < 768; idx += NTH) {
            int tt = idx / 384, rem = idx % 384;
            int d = rem / 12, cb = rem % 12;
            const __nv_bfloat16* src = (tt ? g_vsL : g_vsH)
                + ((size_t)bh * 32 + d) * KKEY + cb * 8;
            CP_ASYNC16(sb + (tt ? OFF_VL0 : OFF_VH0) + d * 208 + cb * 16,
                       (const void*)src);
        }
        CP_COMMIT();
        CP_WAIT0();
        __syncthreads();

        if (w < 8) compute_G(sm, sb, OFF_KB0, w, lane);

#pragma unroll
        for (int i = 0; i < 4; i++)
#pragma unroll
            for (int j = 0; j < 4; j++) acc[i][j] = 0.f;

        for (int kt = 0; kt < NKT; kt++) {
            __syncthreads();   // (A) G(kt) visible; PV(kt-1) done with P/V

            // --- phase C(kt); warps 12-15 prefetch ---
            if (tid < NCHUNK) {
                int qq = tqq[tid], kk = tkk[tid], len = tlen[tid];
                float s = 0.f;
#pragma unroll
                for (int ww = 0; ww < WWIN; ww++)
                    s += G[(qq + ww) * GLD + kk + ww];
                {
                    float p = __expf(s * SCALE);
                    __nv_bfloat16 hi = __float2bfloat16(p);
                    __nv_bfloat16 lo = __float2bfloat16(p - __bfloat162float(hi));
                    int off = qq * QLD + kk;
                    PH[off] = hi;
                    PL[off] = lo;
                }
#pragma unroll 4
                for (int u = 1; u < 32; u++) {
                    int uu = (u < len) ? u : (len - 1);
                    s += G[(qq + uu + 32) * GLD + (kk + uu + 32)]
                       - G[(qq + uu - 1) * GLD + (kk + uu - 1)];
                    if (u < len) {
                        float p = __expf(s * SCALE);
                        __nv_bfloat16 hi = __float2bfloat16(p);
                        __nv_bfloat16 lo = __float2bfloat16(p - __bfloat162float(hi));
                        int off = (qq + u) * QLD + (kk + u);
                        PH[off] = hi;
                        PL[off] = lo;
                    }
                }
            } else if (tid >= 384) {
                int pt = tid - 384;
                if (kt + 2 < NKT) {
                    int k0n = (kt + 2) * TQ;
                    uint32_t kdst = sb + ((kt & 1) ? OFF_KB1 : OFF_KB0);
                    for (int idx = pt; idx < 1536; idx += 128) {
                        int r = idx / 12, cb = idx % 12;
                        CP_ASYNC16(kdst + r * 208 + cb * 16,
                                   (const void*)(ksrc + (size_t)(k0n + r) * 12 + cb));
                    }
                }
                if (kt + 1 < NKT) {
                    int k0n = (kt + 1) * TQ;
                    for (int idx = pt; idx < 768; idx += 128) {
                        int tt = idx / 384, rem = idx % 384;
                        int d = rem / 12, cb = rem % 12;
                        const __nv_bfloat16* src = (tt ? g_vsL : g_vsH)
                            + ((size_t)bh * 32 + d) * KKEY + k0n + cb * 8;
                        int off = tt ? (((kt + 1) & 1) ? OFF_VL1 : OFF_VL0)
                                     : (((kt + 1) & 1) ? OFF_VH1 : OFF_VH0);
                        CP_ASYNC16(sb + off + d * 208 + cb * 16, (const void*)src);
                    }
                }
            }
            CP_COMMIT();
            CP_WAIT1();
            __syncthreads();   // (B) P visible; KB(kt+1)/V(kt) arrived

            // --- overlap: G(kt+1) on warps 0-7, PV(kt) on warps 8-15 ---
            if (w < 8) {
                if (kt + 1 < NKT)
                    compute_G(sm, sb, ((kt + 1) & 1) ? OFF_KB1 : OFF_KB0, w, lane);
            } else {
                uint32_t vhb = sb + ((kt & 1) ? OFF_VH1 : OFF_VH0);
                uint32_t vlb = sb + ((kt & 1) ? OFF_VL1 : OFF_VL0);
                if (w < 14) {
#pragma unroll
                    for (int pass = 0; pass < 3; pass++) {
                        uint32_t Ab = (pass == 1) ? aPLf : aPHf;
                        uint32_t Bb = (pass == 2) ? vlb : vhb;
#pragma unroll
                        for (int ks = 0; ks < 6; ks++) {
                            uint32_t a0, a1, a2, a3;
                            ldsm_x4(Ab + ks * 32, a0, a1, a2, a3);
                            uint32_t b0, b1, b2, b3;
                            ldsm_x4(Bb + bRow4 + ks * 32, b0, b1, b2, b3);
                            mma16816(acc[0], a0, a1, a2, a3, b0, b1);
                            mma16816(acc[1], a0, a1, a2, a3, b2, b3);
                            ldsm_x4(Bb + 16 * 208 + bRow4 + ks * 32, b0, b1, b2, b3);
                            mma16816(acc[2], a0, a1, a2, a3, b0, b1);
                            mma16816(acc[3], a0, a1, a2, a3, b2, b3);
                        }
                    }
                } else {
                    int base = (w - 14) * 3;
#pragma unroll
                    for (int st = 0; st < 3; st++) {
                        uint32_t aPh = sb + OFF_PH
                            + (uint32_t)((base + st) * 16 + (lane & 15)) * 208
                            + (lane >> 4) * 16;
                        uint32_t aPl = aPh + (OFF_PL - OFF_PH);
#pragma unroll
                        for (int pass = 0; pass < 3; pass++) {
                            uint32_t Ab = (pass == 1) ? aPl : aPh;
                            uint32_t Bb = (pass == 2) ? vlb : vhb;
#pragma unroll
                            for (int ks = 0; ks < 6; ks++) {
                                uint32_t a0, a1, a2, a3;
                                ldsm_x4(Ab + ks * 32, a0, a1, a2, a3);
                                uint32_t b0, b1;
                                ldsm_x2(Bb + 32 * 208 + bRow2 + ks * 32, b0, b1);
                                mma16816(acc[st], a0, a1, a2, a3, b0, b1);
                            }
                        }
                    }
                }
            }
        }

        // denominator from warps 14/15 (col 32 -> t==0, j 0/2)
        if (w >= 14 && t == 0) {
            int base = (w - 14) * 3;
#pragma unroll
            for (int st = 0; st < 3; st++) {
                den_s[(base + st) * 16 + g]     = acc[st][0];
                den_s[(base + st) * 16 + g + 8] = acc[st][2];
            }
        }
        __syncthreads();

        if (w >= 8 && w < 14) {
            int stripe = w - 8;
            int b = bh >> 3, h = bh & 7;
#pragma unroll
            for (int mi = 0; mi < 2; mi++) {
                int rr = stripe * 16 + g + mi * 8;
                int q = q0 + rr;
                if (q < SSZ) {
                    float dinv = 1.f / den_s[rr];
                    float* orow = out + ((size_t)b * SSZ + q) * EE + h * 32;
#pragma unroll
                    for (int nt = 0; nt < 4; nt++) {
                        int col = nt * 8 + 2 * t;
                        orow[col]     = acc[nt][mi * 2]     * dinv;
                        orow[col + 1] = acc[nt][mi * 2 + 1] * dinv;
                    }
                }
            }
        }
        if (tid == 0) next_s[0] = atomicAdd(&g_ctr, 1);
        __syncthreads();   // next tile visible; everyone done with QA/P/V/den
        tile = next_s[0];
        if (tile >= NTILES) break;
    }
}

// ---------------------------------------------------------------------------
extern "C" void kernel_launch(void* const* d_in, const int* in_sizes, int n_in,
                              void* d_out, int out_size)
{
    const float* x  = (const float*)d_in[0];
    const float* Wq = (const float*)d_in[1];
    const float* bq = (const float*)d_in[2];
    const float* Wk = (const float*)d_in[3];
    const float* bk = (const float*)d_in[4];
    const float* Wv = (const float*)d_in[5];
    const float* bv = (const float*)d_in[6];
    float* out = (float*)d_out;

    xsplit_kernel<<<(8192 * 64 + 255) / 256, 256>>>(x);
    wsplit_kernel<<<(768 * 256 + 255) / 256, 256>>>(Wq, Wk, Wv);
    ctr_init_kernel<<<1, 1>>>();
    {
        cudaFuncSetAttribute(proj_mma_kernel,
                             cudaFuncAttributeMaxDynamicSharedMemorySize,
                             PJ_SMEM);
        dim3 grid(6, 64);
        proj_mma_kernel<<<grid, 256, PJ_SMEM>>>(bq, bk, bv);
    }
    {
        const int total = NBH * 32 * (KKEY / 8);
        vsum_kernel<<<(total + 255) / 256, 256>>>();
    }
    {
        cudaFuncSetAttribute(attn_kernel,
                             cudaFuncAttributeMaxDynamicSharedMemorySize,
                             SMEM_TOTAL);
        attn_kernel<<<148, NTH, SMEM_TOTAL>>>(out);
    }
}